// round 12
// baseline (speedup 1.0000x reference)
#include <cuda_runtime.h>
#include <cuda_fp16.h>

#define L 4096
#define D 1024
#define H 1024

// ---------------------------------------------------------------------------
// Scratch (__device__ globals; allocation-free rule)
// ---------------------------------------------------------------------------
__device__ __half g_x[(size_t)L * D];        // x fp16
__device__ __half g_wq[(size_t)D * H];       // Wq fp16         [d, h]
__device__ __half g_wk32[(size_t)D * H];     // 32*Wk fp16      [e, h]
__device__ __half g_wvt[(size_t)H * D];      // 32*Wv^T fp16    [h, d]
__device__ __half g_g[(size_t)D * D];        // G = 32*Wk.Wq^T  [e, d]
__device__ __half g_t[(size_t)L * D];        // t = x.G^T       [l, e]
__device__ __half g_vt[(size_t)H * L];       // v^T fp16        [h, l]
__device__ float  g_s[(size_t)L * L];        // G partials / pv partials
__device__ __half g_p[(size_t)L * L];        // P' = exp(S) fp16 (unnormalized)

// ---------------------------------------------------------------------------
// Helpers
// ---------------------------------------------------------------------------
__device__ __forceinline__ unsigned smem_u32(const void* p) {
    unsigned a;
    asm("{ .reg .u64 t; cvta.to.shared.u64 t, %1; cvt.u32.u64 %0, t; }"
        : "=r"(a) : "l"(p));
    return a;
}
__device__ __forceinline__ void cpa16(unsigned dst, const void* src) {
    asm volatile("cp.async.cg.shared.global [%0], [%1], 16;"
                 :: "r"(dst), "l"(src) : "memory");
}
__device__ __forceinline__ void cpa_commit() {
    asm volatile("cp.async.commit_group;" ::: "memory");
}
template <int N>
__device__ __forceinline__ void cpa_wait() {
    asm volatile("cp.async.wait_group %0;" :: "n"(N) : "memory");
}
__device__ __forceinline__ void ldsm4(unsigned& r0, unsigned& r1, unsigned& r2,
                                      unsigned& r3, unsigned addr) {
    asm volatile("ldmatrix.sync.aligned.m8n8.x4.shared.b16 {%0,%1,%2,%3}, [%4];"
                 : "=r"(r0), "=r"(r1), "=r"(r2), "=r"(r3) : "r"(addr));
}
__device__ __forceinline__ void mma_fp(float* c, const unsigned* a,
                                       unsigned b0, unsigned b1) {
    asm volatile(
        "mma.sync.aligned.m16n8k16.row.col.f32.f16.f16.f32 "
        "{%0,%1,%2,%3}, {%4,%5,%6,%7}, {%8,%9}, {%0,%1,%2,%3};"
        : "+f"(c[0]), "+f"(c[1]), "+f"(c[2]), "+f"(c[3])
        : "r"(a[0]), "r"(a[1]), "r"(a[2]), "r"(a[3]), "r"(b0), "r"(b1));
}

// ---------------------------------------------------------------------------
// Single-fp16 128x128 GEMM-NT: C = alpha*(A @ B^T), K range [kBeg, kEnd).
// BK=64 (half the barriers of BK=32). 128 threads, 4 warps (2x2), warp tile
// 64x64; rows padded to 144 B (conflict-free ldmatrix); 2-stage cp.async
// load-after-compute; 2 CTAs/SM.
// EPI: 2 = fp32*alpha row-major | 3 = fp16*alpha row-major
//      5 = fp16*alpha TRANSPOSED   | 6 = fp16 exp(alpha*acc) causal-masked
// ---------------------------------------------------------------------------
#define TILE_B    18432            // 128 rows x 144 B
#define STAGE_B   (2 * TILE_B)     // A, B
#define NT        128
#define SMEM_SZ   (2 * STAGE_B)    // 73728

template <int EPI>
__device__ __forceinline__ void gemm128(
    const __half* __restrict__ A, int lda,
    const __half* __restrict__ B, int ldb,
    void* O0, int ldo, float alpha,
    int m0, int n0, int kBeg, int kEnd)
{
    extern __shared__ char smem_raw[];
    const unsigned sbase = smem_u32(smem_raw);

    const int tid    = threadIdx.x;
    const int wid    = tid >> 5;
    const int lane   = tid & 31;
    const int warp_m = wid >> 1;
    const int warp_n = wid & 1;

    const char* pA = (const char*)(A + (size_t)m0 * lda + kBeg);
    const char* pB = (const char*)(B + (size_t)n0 * ldb + kBeg);

    const int nc = (kEnd - kBeg) >> 6;    // BK=64 chunks

    const int lr0 = tid >> 2;             // 0..31
    const int lc0 = tid & 3;              // base 16B chunk
    auto load_stage = [&](int s) {
        unsigned sb = sbase + (unsigned)(s & 1) * STAGE_B;
        const size_t k0 = (size_t)s * 128;          // bytes
#pragma unroll
        for (int j = 0; j < 4; j++) {
            int r = lr0 + j * 32;
            unsigned so = (unsigned)(r * 144);
            const size_t ga = (size_t)r * lda * 2 + k0;
            const size_t gb = (size_t)r * ldb * 2 + k0;
            cpa16(sb + so + lc0 * 16,                 pA + ga + lc0 * 16);
            cpa16(sb + so + lc0 * 16 + 64,            pA + ga + lc0 * 16 + 64);
            cpa16(sb + TILE_B + so + lc0 * 16,        pB + gb + lc0 * 16);
            cpa16(sb + TILE_B + so + lc0 * 16 + 64,   pB + gb + lc0 * 16 + 64);
        }
    };

    const unsigned aRowOff =
        (unsigned)((warp_m * 64 + (lane & 15)) * 144 + (lane >> 4) * 16);
    const unsigned bRowOff =
        (unsigned)((warp_n * 64 + (lane & 7) + (lane >> 4) * 8) * 144
                   + ((lane >> 3) & 1) * 16);

    float acc[4][8][4];
#pragma unroll
    for (int i = 0; i < 4; i++)
#pragma unroll
        for (int j = 0; j < 8; j++)
#pragma unroll
            for (int k = 0; k < 4; k++) acc[i][j][k] = 0.0f;

    load_stage(0); cpa_commit();
    if (nc > 1) load_stage(1);
    cpa_commit();

    for (int c = 0; c < nc; c++) {
        cpa_wait<1>();
        __syncthreads();

        const unsigned sb  = sbase + (unsigned)(c & 1) * STAGE_B;
        const unsigned sbB = sb + TILE_B;
#pragma unroll
        for (int ks = 0; ks < 4; ks++) {
            unsigned bh[4][4];
#pragma unroll
            for (int g = 0; g < 4; g++) {
                unsigned bd = sbB + bRowOff + g * (16 * 144) + ks * 32;
                ldsm4(bh[g][0], bh[g][1], bh[g][2], bh[g][3], bd);
            }
#pragma unroll
            for (int mi = 0; mi < 4; mi++) {
                unsigned ah[4];
                unsigned ad = sb + aRowOff + mi * (16 * 144) + ks * 32;
                ldsm4(ah[0], ah[1], ah[2], ah[3], ad);
#pragma unroll
                for (int ni = 0; ni < 8; ni++)
                    mma_fp(acc[mi][ni], ah,
                           bh[ni >> 1][(ni & 1) * 2], bh[ni >> 1][(ni & 1) * 2 + 1]);
            }
        }

        __syncthreads();
        if (c + 2 < nc) load_stage(c + 2);
        cpa_commit();
    }

    const int rI = lane >> 2;
    const int cI = (lane & 3) * 2;

    if (EPI == 2) {
        float* O = (float*)O0;
#pragma unroll
        for (int mi = 0; mi < 4; mi++)
#pragma unroll
            for (int ni = 0; ni < 8; ni++) {
                float* a = acc[mi][ni];
                int m = m0 + warp_m * 64 + mi * 16 + rI;
                int n = n0 + warp_n * 64 + ni * 8 + cI;
                float2 v0 = {a[0] * alpha, a[1] * alpha};
                float2 v1 = {a[2] * alpha, a[3] * alpha};
                *(float2*)(O + (size_t)m * ldo + n) = v0;
                *(float2*)(O + (size_t)(m + 8) * ldo + n) = v1;
            }
    } else if (EPI == 3) {
        __half* O = (__half*)O0;
#pragma unroll
        for (int mi = 0; mi < 4; mi++)
#pragma unroll
            for (int ni = 0; ni < 8; ni++) {
                float* a = acc[mi][ni];
                int m = m0 + warp_m * 64 + mi * 16 + rI;
                int n = n0 + warp_n * 64 + ni * 8 + cI;
                *(__half2*)(O + (size_t)m * ldo + n) =
                    __floats2half2_rn(a[0] * alpha, a[1] * alpha);
                *(__half2*)(O + (size_t)(m + 8) * ldo + n) =
                    __floats2half2_rn(a[2] * alpha, a[3] * alpha);
            }
    } else if (EPI == 6) {          // exp(alpha*acc), causal mask n > m -> 0
        __half* O = (__half*)O0;
#pragma unroll
        for (int mi = 0; mi < 4; mi++)
#pragma unroll
            for (int ni = 0; ni < 8; ni++) {
                float* a = acc[mi][ni];
                int m = m0 + warp_m * 64 + mi * 16 + rI;
                int n = n0 + warp_n * 64 + ni * 8 + cI;
                float e0 = (n     <= m) ? __expf(a[0] * alpha) : 0.0f;
                float e1 = (n + 1 <= m) ? __expf(a[1] * alpha) : 0.0f;
                *(__half2*)(O + (size_t)m * ldo + n) = __floats2half2_rn(e0, e1);
                int m8 = m + 8;
                float e2 = (n     <= m8) ? __expf(a[2] * alpha) : 0.0f;
                float e3 = (n + 1 <= m8) ? __expf(a[3] * alpha) : 0.0f;
                *(__half2*)(O + (size_t)m8 * ldo + n) = __floats2half2_rn(e2, e3);
            }
    } else {  // EPI == 5: fp16 transposed (via fp32 smem staging [128][132])
        __syncthreads();
        float* T = (float*)smem_raw;          // 67584 B < SMEM_SZ
#pragma unroll
        for (int mi = 0; mi < 4; mi++)
#pragma unroll
            for (int ni = 0; ni < 8; ni++) {
                float* a = acc[mi][ni];
                int lm = warp_m * 64 + mi * 16 + rI;
                int ln = warp_n * 64 + ni * 8 + cI;
                T[lm * 132 + ln]           = a[0];
                T[lm * 132 + ln + 1]       = a[1];
                T[(lm + 8) * 132 + ln]     = a[2];
                T[(lm + 8) * 132 + ln + 1] = a[3];
            }
        __syncthreads();
        __half* O = (__half*)O0;
        const int n = tid;
#pragma unroll
        for (int i = 0; i < 128; i += 8) {
            __half hp[8];
#pragma unroll
            for (int j = 0; j < 8; j++)
                hp[j] = __float2half_rn(T[(i + j) * 132 + n] * alpha);
            size_t o = (size_t)(n0 + n) * ldo + m0 + i;
            *(uint4*)(O + o) = *(uint4*)hp;
        }
    }
}

// ---------------------------------------------------------------------------
// Stage 0: all conversions in one launch.
// ---------------------------------------------------------------------------
__global__ __launch_bounds__(256) void k_conv(
    const float* __restrict__ x,  const float* __restrict__ Wq,
    const float* __restrict__ Wk, const float* __restrict__ Wv)
{
    __shared__ float t[32][33];
    const int b = blockIdx.x;
    const int tid = threadIdx.x;
    if (b < 4096) {
        size_t i = ((size_t)b * 256 + tid) * 4;
        float4 v = *(const float4*)(x + i);
        *(__half2*)(g_x + i)     = __floats2half2_rn(v.x, v.y);
        *(__half2*)(g_x + i + 2) = __floats2half2_rn(v.z, v.w);
    } else if (b < 5120) {
        size_t i = ((size_t)(b - 4096) * 256 + tid) * 4;
        float4 v = *(const float4*)(Wq + i);
        *(__half2*)(g_wq + i)     = __floats2half2_rn(v.x, v.y);
        *(__half2*)(g_wq + i + 2) = __floats2half2_rn(v.z, v.w);
    } else if (b < 6144) {
        size_t i = ((size_t)(b - 5120) * 256 + tid) * 4;
        float4 v = *(const float4*)(Wk + i);
        *(__half2*)(g_wk32 + i)     = __floats2half2_rn(v.x * 32.f, v.y * 32.f);
        *(__half2*)(g_wk32 + i + 2) = __floats2half2_rn(v.z * 32.f, v.w * 32.f);
    } else {
        const int u  = b - 6144;
        const int h0 = (u & 31) * 32, d0 = (u >> 5) * 32;
        const int tx = tid & 31, ty = tid >> 5;
        for (int i = ty; i < 32; i += 8)
            t[i][tx] = Wv[(size_t)(d0 + i) * H + h0 + tx];
        __syncthreads();
        for (int i = ty; i < 32; i += 8)
            g_wvt[(size_t)(h0 + i) * D + d0 + tx] = __float2half_rn(t[tx][i] * 32.f);
    }
}

// ---------------------------------------------------------------------------
// Stage 1: merged: y<32 -> v^T tiles (16 chunks); y>=32 -> G split-K4 pieces
// ---------------------------------------------------------------------------
__global__ __launch_bounds__(NT, 2) void k_vg()
{
    const int by = blockIdx.y, bx = blockIdx.x;
    if (by < 32) {
        gemm128<5>(g_x, D, g_wvt, D, (void*)g_vt, L, 0.03125f,
                   by * 128, bx * 128, 0, D);
    } else {
        const int yy = by - 32;
        const int gm = yy >> 2;
        const int j  = yy & 3;
        float* O = (float*)g_s + (size_t)j * (D * D);
        gemm128<2>(g_wk32, H, g_wq, H, (void*)O, D, 1.0f,
                   gm * 128, bx * 128, j * 256, j * 256 + 256);
    }
}

__global__ __launch_bounds__(256) void k_gred()
{
    size_t i = ((size_t)blockIdx.x * 256 + threadIdx.x) * 4;
    const float* s = (const float*)g_s;
    float4 a = *(const float4*)(s + i);
    float4 b = *(const float4*)(s + (size_t)D * D + i);
    float4 c = *(const float4*)(s + (size_t)2 * D * D + i);
    float4 d = *(const float4*)(s + (size_t)3 * D * D + i);
    *(__half2*)(g_g + i)     = __floats2half2_rn(a.x + b.x + c.x + d.x,
                                                 a.y + b.y + c.y + d.y);
    *(__half2*)(g_g + i + 2) = __floats2half2_rn(a.z + b.z + c.z + d.z,
                                                 a.w + b.w + c.w + d.w);
}

// ---------------------------------------------------------------------------
// Stage 2: t = x (x) G
// ---------------------------------------------------------------------------
__global__ __launch_bounds__(NT, 2) void k_t()
{
    gemm128<3>(g_x, D, g_g, D, (void*)g_t, D, 1.0f,
               blockIdx.y * 128, blockIdx.x * 128, 0, D);
}

// ---------------------------------------------------------------------------
// Stage 3: P' = exp(t.x^T / 1024) with causal mask, lower-triangular tiles
// ---------------------------------------------------------------------------
__global__ __launch_bounds__(NT, 2) void k_scores()
{
    if (blockIdx.x > blockIdx.y) return;
    gemm128<6>(g_t, D, g_x, D, (void*)g_p, L, 1.0f / 1024.0f,
               blockIdx.y * 128, blockIdx.x * 128, 0, D);
}

// ---------------------------------------------------------------------------
// Stage 4: out = P' @ v (unnormalized), balanced split-K (64-granular).
// np(bi)=bi/8+1; long pieces first. j=0 -> out; j>=1 -> scratch slots in g_s.
// ---------------------------------------------------------------------------
__global__ __launch_bounds__(NT, 2) void k_pv(float* __restrict__ out)
{
    const int y = blockIdx.y, x = blockIdx.x;
    int bi, j, np;
    if (y < 32)      { bi = 31 - (y >> 2);        j = y & 3;          np = 4; }
    else if (y < 56) { int u = y - 32; bi = 23 - u / 3; j = u % 3;    np = 3; }
    else if (y < 72) { int u = y - 56; bi = 15 - (u >> 1); j = u & 1; np = 2; }
    else             { bi = 7 - (y - 72);         j = 0;              np = 1; }

    const int Kc = (bi + 1) * 2;                  // 64-chunks for this row
    const int kb = (j * Kc) / np * 64;
    const int ke = ((j + 1) * Kc) / np * 64;
    const int m0 = bi * 128, n0 = x * 128;

    if (j == 0) {
        gemm128<2>(g_p, L, g_vt, L, (void*)out, H, 1.0f, m0, n0, kb, ke);
    } else {
        int sl;
        if (bi < 16)      sl = bi - 8;
        else if (bi < 24) sl = 8 + (bi - 16) * 2 + (j - 1);
        else              sl = 24 + (bi - 24) * 3 + (j - 1);
        float* base = (float*)g_s + (size_t)(sl * 8 + x) * 16384;
        float* O = base - (size_t)m0 * 128 - n0;
        gemm128<2>(g_p, L, g_vt, L, (void*)O, 128, 1.0f, m0, n0, kb, ke);
    }
}

// ---------------------------------------------------------------------------
// Stage 5: one block per output row m: rowsum(P'[m]) -> inv, merge split-K
// partials, scale. (fused rowsum + pvscale)
// ---------------------------------------------------------------------------
__global__ __launch_bounds__(256) void k_pvscale(float* __restrict__ out)
{
    __shared__ float red[256];
    const int m   = blockIdx.x;
    const int tid = threadIdx.x;
    const int end = ((m >> 7) + 1) << 7;

    // rowsum of P' row m
    const __half* p = g_p + (size_t)m * L;
    float acc = 0.0f;
    for (int i = tid * 2; i < end; i += 512) {
        __half2 v = *(const __half2*)(p + i);
        float2 f = __half22float2(v);
        acc += f.x + f.y;
    }
    red[tid] = acc;
    __syncthreads();
    for (int s = 128; s > 0; s >>= 1) {
        if (tid < s) red[tid] += red[tid + s];
        __syncthreads();
    }
    const float inv = 1.0f / red[0];

    // merge partials + scale (4 floats per thread = H)
    const int n  = tid * 4;
    const int bi = m >> 7;
    const int np = (bi >> 3) + 1;
    size_t oi = (size_t)m * H + n;

    float4 a = *(float4*)(out + oi);
    if (np > 1) {
        const int r128 = m & 127;
        const int xt = n >> 7;
        const int nl = n & 127;
        const float* s = (const float*)g_s;
#pragma unroll 3
        for (int j = 1; j < 4; j++) {
            if (j >= np) break;
            int sl;
            if (bi < 16)      sl = bi - 8;
            else if (bi < 24) sl = 8 + (bi - 16) * 2 + (j - 1);
            else              sl = 24 + (bi - 24) * 3 + (j - 1);
            const float* b = s + (size_t)(sl * 8 + xt) * 16384 + r128 * 128 + nl;
            float4 v = *(const float4*)b;
            a.x += v.x; a.y += v.y; a.z += v.z; a.w += v.w;
        }
    }
    a.x *= inv; a.y *= inv; a.z *= inv; a.w *= inv;
    *(float4*)(out + oi) = a;
}

// ---------------------------------------------------------------------------
extern "C" void kernel_launch(void* const* d_in, const int* in_sizes, int n_in,
                              void* d_out, int out_size)
{
    const float* x  = (const float*)d_in[0];
    // d_in[1] = mask (structurally triu(k=1); causality handled directly)
    const float* Wq = (const float*)d_in[2];
    const float* Wk = (const float*)d_in[3];
    const float* Wv = (const float*)d_in[4];
    float* out = (float*)d_out;

    cudaFuncSetAttribute(k_vg,     cudaFuncAttributeMaxDynamicSharedMemorySize, SMEM_SZ);
    cudaFuncSetAttribute(k_t,      cudaFuncAttributeMaxDynamicSharedMemorySize, SMEM_SZ);
    cudaFuncSetAttribute(k_scores, cudaFuncAttributeMaxDynamicSharedMemorySize, SMEM_SZ);
    cudaFuncSetAttribute(k_pv,     cudaFuncAttributeMaxDynamicSharedMemorySize, SMEM_SZ);

    k_conv<<<7168, 256>>>(x, Wq, Wk, Wv);
    k_vg<<<dim3(8, 64), NT, SMEM_SZ>>>();
    k_gred<<<(D * D) / 1024, 256>>>();
    k_t<<<dim3(8, 32), NT, SMEM_SZ>>>();
    k_scores<<<dim3(32, 32), NT, SMEM_SZ>>>();
    k_pv<<<dim3(8, 80), NT, SMEM_SZ>>>(out);
    k_pvscale<<<L, 256>>>(out);
}

// round 13
// speedup vs baseline: 1.0629x; 1.0629x over previous
#include <cuda_runtime.h>
#include <cuda_fp16.h>

#define L 4096
#define D 1024
#define H 1024

// ---------------------------------------------------------------------------
// Scratch (__device__ globals; allocation-free rule)
// ---------------------------------------------------------------------------
__device__ __half g_x[(size_t)L * D];        // x fp16
__device__ __half g_wq[(size_t)D * H];       // Wq fp16         [d, h]
__device__ __half g_wk32[(size_t)D * H];     // 32*Wk fp16      [e, h]
__device__ __half g_wvt[(size_t)H * D];      // 32*Wv^T fp16    [h, d]
__device__ __half g_g[(size_t)D * D];        // G = 32*Wk.Wq^T  [e, d]
__device__ __half g_t[(size_t)L * D];        // t = x.G^T       [l, e]
__device__ __half g_vt[(size_t)H * L];       // v^T fp16        [h, l]
__device__ float  g_s[(size_t)L * L];        // G partials / pv partials
__device__ __half g_p[(size_t)L * L];        // P' = exp(S) fp16 (unnormalized)

// ---------------------------------------------------------------------------
// Helpers
// ---------------------------------------------------------------------------
__device__ __forceinline__ unsigned smem_u32(const void* p) {
    unsigned a;
    asm("{ .reg .u64 t; cvta.to.shared.u64 t, %1; cvt.u32.u64 %0, t; }"
        : "=r"(a) : "l"(p));
    return a;
}
__device__ __forceinline__ void cpa16(unsigned dst, const void* src) {
    asm volatile("cp.async.cg.shared.global [%0], [%1], 16;"
                 :: "r"(dst), "l"(src) : "memory");
}
__device__ __forceinline__ void cpa_commit() {
    asm volatile("cp.async.commit_group;" ::: "memory");
}
template <int N>
__device__ __forceinline__ void cpa_wait() {
    asm volatile("cp.async.wait_group %0;" :: "n"(N) : "memory");
}
__device__ __forceinline__ void ldsm4(unsigned& r0, unsigned& r1, unsigned& r2,
                                      unsigned& r3, unsigned addr) {
    asm volatile("ldmatrix.sync.aligned.m8n8.x4.shared.b16 {%0,%1,%2,%3}, [%4];"
                 : "=r"(r0), "=r"(r1), "=r"(r2), "=r"(r3) : "r"(addr));
}
__device__ __forceinline__ void mma_fp(float* c, const unsigned* a,
                                       unsigned b0, unsigned b1) {
    asm volatile(
        "mma.sync.aligned.m16n8k16.row.col.f32.f16.f16.f32 "
        "{%0,%1,%2,%3}, {%4,%5,%6,%7}, {%8,%9}, {%0,%1,%2,%3};"
        : "+f"(c[0]), "+f"(c[1]), "+f"(c[2]), "+f"(c[3])
        : "r"(a[0]), "r"(a[1]), "r"(a[2]), "r"(a[3]), "r"(b0), "r"(b1));
}

// ---------------------------------------------------------------------------
// Single-fp16 128x128 GEMM-NT (R11-proven engine — FROZEN):
// C = alpha*(A @ B^T), K range [kBeg, kEnd). 128 threads, 4 warps (2x2),
// warp tile 64x64; pad-80 smem rows; BK=32; 2-stage cp.async
// load-after-compute; 2 CTAs/SM.
// EPI: 2 = fp32*alpha row-major | 3 = fp16*alpha row-major
//      5 = fp16*alpha TRANSPOSED   | 6 = fp16 exp(alpha*acc) causal-masked
// ---------------------------------------------------------------------------
#define TILE_B    10240            // 128 rows x 40 halves (pad)
#define STAGE_B   (2 * TILE_B)
#define NT        128
#define SMEM_G    (2 * STAGE_B)    // 40960
#define SMEM_QKV  67584            // [128][132] fp32 transpose staging

template <int EPI>
__device__ __forceinline__ void gemm128(
    const __half* __restrict__ A, int lda,
    const __half* __restrict__ B, int ldb,
    void* O0, int ldo, float alpha,
    int m0, int n0, int kBeg, int kEnd)
{
    extern __shared__ char smem_raw[];
    const unsigned sbase = smem_u32(smem_raw);

    const int tid    = threadIdx.x;
    const int wid    = tid >> 5;
    const int lane   = tid & 31;
    const int warp_m = wid >> 1;
    const int warp_n = wid & 1;

    const char* pA = (const char*)(A + (size_t)m0 * lda + kBeg);
    const char* pB = (const char*)(B + (size_t)n0 * ldb + kBeg);

    const int nc = (kEnd - kBeg) >> 5;

    const int lr0 = tid >> 2;
    const int lcc = tid & 3;
    auto load_stage = [&](int s) {
        unsigned sb = sbase + (unsigned)(s & 1) * STAGE_B;
        const size_t kof = (size_t)s * 64 + lcc * 16;
#pragma unroll
        for (int j = 0; j < 4; j++) {
            int r = lr0 + j * 32;
            unsigned so = (unsigned)(r * 80 + lcc * 16);
            cpa16(sb + so,          pA + (size_t)r * lda * 2 + kof);
            cpa16(sb + TILE_B + so, pB + (size_t)r * ldb * 2 + kof);
        }
    };

    const unsigned aRowOff =
        (unsigned)((warp_m * 64 + (lane & 15)) * 80 + (lane >> 4) * 16);
    const unsigned bRowOff =
        (unsigned)((warp_n * 64 + (lane & 7) + (lane >> 4) * 8) * 80
                   + ((lane >> 3) & 1) * 16);

    float acc[4][8][4];
#pragma unroll
    for (int i = 0; i < 4; i++)
#pragma unroll
        for (int j = 0; j < 8; j++)
#pragma unroll
            for (int k = 0; k < 4; k++) acc[i][j][k] = 0.0f;

    load_stage(0); cpa_commit();
    if (nc > 1) load_stage(1);
    cpa_commit();

    for (int c = 0; c < nc; c++) {
        cpa_wait<1>();
        __syncthreads();

        const unsigned sb  = sbase + (unsigned)(c & 1) * STAGE_B;
        const unsigned sbB = sb + TILE_B;
#pragma unroll
        for (int ks = 0; ks < 2; ks++) {
            unsigned bh[4][4];
#pragma unroll
            for (int g = 0; g < 4; g++) {
                unsigned bd = sbB + bRowOff + g * 1280 + ks * 32;
                ldsm4(bh[g][0], bh[g][1], bh[g][2], bh[g][3], bd);
            }
#pragma unroll
            for (int mi = 0; mi < 4; mi++) {
                unsigned ah[4];
                unsigned ad = sb + aRowOff + mi * 1280 + ks * 32;
                ldsm4(ah[0], ah[1], ah[2], ah[3], ad);
#pragma unroll
                for (int ni = 0; ni < 8; ni++)
                    mma_fp(acc[mi][ni], ah,
                           bh[ni >> 1][(ni & 1) * 2], bh[ni >> 1][(ni & 1) * 2 + 1]);
            }
        }

        __syncthreads();
        if (c + 2 < nc) load_stage(c + 2);
        cpa_commit();
    }

    const int rI = lane >> 2;
    const int cI = (lane & 3) * 2;

    if (EPI == 2) {
        float* O = (float*)O0;
#pragma unroll
        for (int mi = 0; mi < 4; mi++)
#pragma unroll
            for (int ni = 0; ni < 8; ni++) {
                float* a = acc[mi][ni];
                int m = m0 + warp_m * 64 + mi * 16 + rI;
                int n = n0 + warp_n * 64 + ni * 8 + cI;
                float2 v0 = {a[0] * alpha, a[1] * alpha};
                float2 v1 = {a[2] * alpha, a[3] * alpha};
                *(float2*)(O + (size_t)m * ldo + n) = v0;
                *(float2*)(O + (size_t)(m + 8) * ldo + n) = v1;
            }
    } else if (EPI == 3) {
        __half* O = (__half*)O0;
#pragma unroll
        for (int mi = 0; mi < 4; mi++)
#pragma unroll
            for (int ni = 0; ni < 8; ni++) {
                float* a = acc[mi][ni];
                int m = m0 + warp_m * 64 + mi * 16 + rI;
                int n = n0 + warp_n * 64 + ni * 8 + cI;
                *(__half2*)(O + (size_t)m * ldo + n) =
                    __floats2half2_rn(a[0] * alpha, a[1] * alpha);
                *(__half2*)(O + (size_t)(m + 8) * ldo + n) =
                    __floats2half2_rn(a[2] * alpha, a[3] * alpha);
            }
    } else if (EPI == 6) {          // exp(alpha*acc), causal mask n > m -> 0
        __half* O = (__half*)O0;
#pragma unroll
        for (int mi = 0; mi < 4; mi++)
#pragma unroll
            for (int ni = 0; ni < 8; ni++) {
                float* a = acc[mi][ni];
                int m = m0 + warp_m * 64 + mi * 16 + rI;
                int n = n0 + warp_n * 64 + ni * 8 + cI;
                float e0 = (n     <= m) ? __expf(a[0] * alpha) : 0.0f;
                float e1 = (n + 1 <= m) ? __expf(a[1] * alpha) : 0.0f;
                *(__half2*)(O + (size_t)m * ldo + n) = __floats2half2_rn(e0, e1);
                int m8 = m + 8;
                float e2 = (n     <= m8) ? __expf(a[2] * alpha) : 0.0f;
                float e3 = (n + 1 <= m8) ? __expf(a[3] * alpha) : 0.0f;
                *(__half2*)(O + (size_t)m8 * ldo + n) = __floats2half2_rn(e2, e3);
            }
    } else {  // EPI == 5: fp16 transposed (via fp32 smem staging [128][132])
        __syncthreads();
        float* T = (float*)smem_raw;
#pragma unroll
        for (int mi = 0; mi < 4; mi++)
#pragma unroll
            for (int ni = 0; ni < 8; ni++) {
                float* a = acc[mi][ni];
                int lm = warp_m * 64 + mi * 16 + rI;
                int ln = warp_n * 64 + ni * 8 + cI;
                T[lm * 132 + ln]           = a[0];
                T[lm * 132 + ln + 1]       = a[1];
                T[(lm + 8) * 132 + ln]     = a[2];
                T[(lm + 8) * 132 + ln + 1] = a[3];
            }
        __syncthreads();
        __half* O = (__half*)O0;
        const int n = tid;
#pragma unroll
        for (int i = 0; i < 128; i += 8) {
            __half hp[8];
#pragma unroll
            for (int j = 0; j < 8; j++)
                hp[j] = __float2half_rn(T[(i + j) * 132 + n] * alpha);
            size_t o = (size_t)(n0 + n) * ldo + m0 + i;
            *(uint4*)(O + o) = *(uint4*)hp;
        }
    }
}

// ---------------------------------------------------------------------------
// Stage 0: all conversions in one launch.
// ---------------------------------------------------------------------------
__global__ __launch_bounds__(256) void k_conv(
    const float* __restrict__ x,  const float* __restrict__ Wq,
    const float* __restrict__ Wk, const float* __restrict__ Wv)
{
    __shared__ float t[32][33];
    const int b = blockIdx.x;
    const int tid = threadIdx.x;
    if (b < 4096) {
        size_t i = ((size_t)b * 256 + tid) * 4;
        float4 v = *(const float4*)(x + i);
        *(__half2*)(g_x + i)     = __floats2half2_rn(v.x, v.y);
        *(__half2*)(g_x + i + 2) = __floats2half2_rn(v.z, v.w);
    } else if (b < 5120) {
        size_t i = ((size_t)(b - 4096) * 256 + tid) * 4;
        float4 v = *(const float4*)(Wq + i);
        *(__half2*)(g_wq + i)     = __floats2half2_rn(v.x, v.y);
        *(__half2*)(g_wq + i + 2) = __floats2half2_rn(v.z, v.w);
    } else if (b < 6144) {
        size_t i = ((size_t)(b - 5120) * 256 + tid) * 4;
        float4 v = *(const float4*)(Wk + i);
        *(__half2*)(g_wk32 + i)     = __floats2half2_rn(v.x * 32.f, v.y * 32.f);
        *(__half2*)(g_wk32 + i + 2) = __floats2half2_rn(v.z * 32.f, v.w * 32.f);
    } else {
        const int u  = b - 6144;
        const int h0 = (u & 31) * 32, d0 = (u >> 5) * 32;
        const int tx = tid & 31, ty = tid >> 5;
        for (int i = ty; i < 32; i += 8)
            t[i][tx] = Wv[(size_t)(d0 + i) * H + h0 + tx];
        __syncthreads();
        for (int i = ty; i < 32; i += 8)
            g_wvt[(size_t)(h0 + i) * D + d0 + tx] = __float2half_rn(t[tx][i] * 32.f);
    }
}

// ---------------------------------------------------------------------------
// Stage 1: merged: y<32 -> v^T tiles (32 chunks); y>=32 -> G split-K4 pieces
// ---------------------------------------------------------------------------
__global__ __launch_bounds__(NT, 2) void k_vg()
{
    const int by = blockIdx.y, bx = blockIdx.x;
    if (by < 32) {
        gemm128<5>(g_x, D, g_wvt, D, (void*)g_vt, L, 0.03125f,
                   by * 128, bx * 128, 0, D);
    } else {
        const int yy = by - 32;
        const int gm = yy >> 2;
        const int j  = yy & 3;
        float* O = (float*)g_s + (size_t)j * (D * D);
        gemm128<2>(g_wk32, H, g_wq, H, (void*)O, D, 1.0f,
                   gm * 128, bx * 128, j * 256, j * 256 + 256);
    }
}

__global__ __launch_bounds__(256) void k_gred()
{
    size_t i = ((size_t)blockIdx.x * 256 + threadIdx.x) * 4;
    const float* s = (const float*)g_s;
    float4 a = *(const float4*)(s + i);
    float4 b = *(const float4*)(s + (size_t)D * D + i);
    float4 c = *(const float4*)(s + (size_t)2 * D * D + i);
    float4 d = *(const float4*)(s + (size_t)3 * D * D + i);
    *(__half2*)(g_g + i)     = __floats2half2_rn(a.x + b.x + c.x + d.x,
                                                 a.y + b.y + c.y + d.y);
    *(__half2*)(g_g + i + 2) = __floats2half2_rn(a.z + b.z + c.z + d.z,
                                                 a.w + b.w + c.w + d.w);
}

// ---------------------------------------------------------------------------
// Stage 2: t = x (x) G
// ---------------------------------------------------------------------------
__global__ __launch_bounds__(NT, 2) void k_t()
{
    gemm128<3>(g_x, D, g_g, D, (void*)g_t, D, 1.0f,
               blockIdx.y * 128, blockIdx.x * 128, 0, D);
}

// ---------------------------------------------------------------------------
// Stage 3: P' = exp(t.x^T / 1024) with causal mask.
// 1-D triangular grid: exactly 528 CTAs, u -> (by, bx) with bx <= by.
// ---------------------------------------------------------------------------
__global__ __launch_bounds__(NT, 2) void k_scores()
{
    const int u = blockIdx.x;
    int by = (int)((__fsqrt_rn(8.0f * (float)u + 1.0f) - 1.0f) * 0.5f);
    while ((by + 1) * (by + 2) / 2 <= u) by++;
    while (by * (by + 1) / 2 > u)        by--;
    const int bx = u - by * (by + 1) / 2;
    gemm128<6>(g_t, D, g_x, D, (void*)g_p, L, 1.0f / 1024.0f,
               by * 128, bx * 128, 0, D);
}

// ---------------------------------------------------------------------------
// Stage 4: out = P' @ v (unnormalized), balanced split-K (pieces <= 32 chunks)
// np(bi)=bi/8+1; long pieces first. j=0 -> out; j>=1 -> scratch slots in g_s.
// ---------------------------------------------------------------------------
__global__ __launch_bounds__(NT, 2) void k_pv(float* __restrict__ out)
{
    const int y = blockIdx.y, x = blockIdx.x;
    int bi, j, np;
    if (y < 32)      { bi = 31 - (y >> 2);        j = y & 3;          np = 4; }
    else if (y < 56) { int u = y - 32; bi = 23 - u / 3; j = u % 3;    np = 3; }
    else if (y < 72) { int u = y - 56; bi = 15 - (u >> 1); j = u & 1; np = 2; }
    else             { bi = 7 - (y - 72);         j = 0;              np = 1; }

    const int Kc = (bi + 1) * 4;
    const int kb = (j * Kc) / np * 32;
    const int ke = ((j + 1) * Kc) / np * 32;
    const int m0 = bi * 128, n0 = x * 128;

    if (j == 0) {
        gemm128<2>(g_p, L, g_vt, L, (void*)out, H, 1.0f, m0, n0, kb, ke);
    } else {
        int sl;
        if (bi < 16)      sl = bi - 8;
        else if (bi < 24) sl = 8 + (bi - 16) * 2 + (j - 1);
        else              sl = 24 + (bi - 24) * 3 + (j - 1);
        float* base = (float*)g_s + (size_t)(sl * 8 + x) * 16384;
        float* O = base - (size_t)m0 * 128 - n0;
        gemm128<2>(g_p, L, g_vt, L, (void*)O, 128, 1.0f, m0, n0, kb, ke);
    }
}

// ---------------------------------------------------------------------------
// Stage 5: one block per output row m: rowsum(P'[m]) -> inv, merge split-K
// partials, scale. (fused rowsum + pvscale)
// ---------------------------------------------------------------------------
__global__ __launch_bounds__(256) void k_pvscale(float* __restrict__ out)
{
    __shared__ float red[256];
    const int m   = blockIdx.x;
    const int tid = threadIdx.x;
    const int end = ((m >> 7) + 1) << 7;

    const __half* p = g_p + (size_t)m * L;
    float acc = 0.0f;
    for (int i = tid * 2; i < end; i += 512) {
        __half2 v = *(const __half2*)(p + i);
        float2 f = __half22float2(v);
        acc += f.x + f.y;
    }
    red[tid] = acc;
    __syncthreads();
    for (int s = 128; s > 0; s >>= 1) {
        if (tid < s) red[tid] += red[tid + s];
        __syncthreads();
    }
    const float inv = 1.0f / red[0];

    const int n  = tid * 4;
    const int bi = m >> 7;
    const int np = (bi >> 3) + 1;
    size_t oi = (size_t)m * H + n;

    float4 a = *(float4*)(out + oi);
    if (np > 1) {
        const int r128 = m & 127;
        const int xt = n >> 7;
        const int nl = n & 127;
        const float* s = (const float*)g_s;
#pragma unroll 3
        for (int j = 1; j < 4; j++) {
            if (j >= np) break;
            int sl;
            if (bi < 16)      sl = bi - 8;
            else if (bi < 24) sl = 8 + (bi - 16) * 2 + (j - 1);
            else              sl = 24 + (bi - 24) * 3 + (j - 1);
            const float* b = s + (size_t)(sl * 8 + xt) * 16384 + r128 * 128 + nl;
            float4 v = *(const float4*)b;
            a.x += v.x; a.y += v.y; a.z += v.z; a.w += v.w;
        }
    }
    a.x *= inv; a.y *= inv; a.z *= inv; a.w *= inv;
    *(float4*)(out + oi) = a;
}

// ---------------------------------------------------------------------------
extern "C" void kernel_launch(void* const* d_in, const int* in_sizes, int n_in,
                              void* d_out, int out_size)
{
    const float* x  = (const float*)d_in[0];
    // d_in[1] = mask (structurally triu(k=1); causality handled directly)
    const float* Wq = (const float*)d_in[2];
    const float* Wk = (const float*)d_in[3];
    const float* Wv = (const float*)d_in[4];
    float* out = (float*)d_out;

    cudaFuncSetAttribute(k_vg, cudaFuncAttributeMaxDynamicSharedMemorySize, SMEM_QKV);

    k_conv<<<7168, 256>>>(x, Wq, Wk, Wv);
    k_vg<<<dim3(8, 64), NT, SMEM_QKV>>>();
    k_gred<<<(D * D) / 1024, 256>>>();
    k_t<<<dim3(8, 32), NT, SMEM_G>>>();
    k_scores<<<528, NT, SMEM_G>>>();
    k_pv<<<dim3(8, 80), NT, SMEM_G>>>(out);
    k_pvscale<<<L, 256>>>(out);
}

// round 14
// speedup vs baseline: 1.0703x; 1.0069x over previous
#include <cuda_runtime.h>
#include <cuda_fp16.h>

#define L 4096
#define D 1024
#define H 1024

// ---------------------------------------------------------------------------
// Scratch (__device__ globals; allocation-free rule)
// ---------------------------------------------------------------------------
__device__ __half g_x[(size_t)L * D];        // x fp16
__device__ __half g_wq[(size_t)D * H];       // Wq fp16         [d, h]
__device__ __half g_wk32[(size_t)D * H];     // 32*Wk fp16      [e, h]
__device__ __half g_wvt[(size_t)H * D];      // 32*Wv^T fp16    [h, d]
__device__ __half g_g[(size_t)D * D];        // G = 32*Wk.Wq^T  [e, d]
__device__ __half g_t[(size_t)L * D];        // t = x.G^T       [l, e]
__device__ __half g_vt[(size_t)H * L];       // v^T fp16        [h, l]
__device__ float  g_s[(size_t)L * L];        // G partials / pv partials
__device__ __half g_p[(size_t)L * L];        // P' = exp(S) fp16 (unnormalized)

// ---------------------------------------------------------------------------
// Helpers
// ---------------------------------------------------------------------------
__device__ __forceinline__ unsigned smem_u32(const void* p) {
    unsigned a;
    asm("{ .reg .u64 t; cvta.to.shared.u64 t, %1; cvt.u32.u64 %0, t; }"
        : "=r"(a) : "l"(p));
    return a;
}
__device__ __forceinline__ void cpa16(unsigned dst, const void* src) {
    asm volatile("cp.async.cg.shared.global [%0], [%1], 16;"
                 :: "r"(dst), "l"(src) : "memory");
}
__device__ __forceinline__ void cpa_commit() {
    asm volatile("cp.async.commit_group;" ::: "memory");
}
template <int N>
__device__ __forceinline__ void cpa_wait() {
    asm volatile("cp.async.wait_group %0;" :: "n"(N) : "memory");
}
__device__ __forceinline__ void ldsm4(unsigned& r0, unsigned& r1, unsigned& r2,
                                      unsigned& r3, unsigned addr) {
    asm volatile("ldmatrix.sync.aligned.m8n8.x4.shared.b16 {%0,%1,%2,%3}, [%4];"
                 : "=r"(r0), "=r"(r1), "=r"(r2), "=r"(r3) : "r"(addr));
}
__device__ __forceinline__ void mma_fp(float* c, const unsigned* a,
                                       unsigned b0, unsigned b1) {
    asm volatile(
        "mma.sync.aligned.m16n8k16.row.col.f32.f16.f16.f32 "
        "{%0,%1,%2,%3}, {%4,%5,%6,%7}, {%8,%9}, {%0,%1,%2,%3};"
        : "+f"(c[0]), "+f"(c[1]), "+f"(c[2]), "+f"(c[3])
        : "r"(a[0]), "r"(a[1]), "r"(a[2]), "r"(a[3]), "r"(b0), "r"(b1));
}

// ---------------------------------------------------------------------------
// Single-fp16 128x128 GEMM-NT (R11-proven engine — FROZEN):
// C = alpha*(A @ B^T), K range [kBeg, kEnd). 128 threads, 4 warps (2x2),
// warp tile 64x64; pad-80 smem rows; BK=32; 2-stage cp.async
// load-after-compute; 2 CTAs/SM.
// EPI: 2 = fp32*alpha row-major | 3 = fp16*alpha row-major
//      5 = fp16*alpha TRANSPOSED   | 6 = fp16 exp(alpha*acc) causal-masked
// ---------------------------------------------------------------------------
#define TILE_B    10240            // 128 rows x 40 halves (pad)
#define STAGE_B   (2 * TILE_B)
#define NT        128
#define SMEM_G    (2 * STAGE_B)    // 40960
#define SMEM_QKV  67584            // [128][132] fp32 transpose staging

template <int EPI>
__device__ __forceinline__ void gemm128(
    const __half* __restrict__ A, int lda,
    const __half* __restrict__ B, int ldb,
    void* O0, int ldo, float alpha,
    int m0, int n0, int kBeg, int kEnd)
{
    extern __shared__ char smem_raw[];
    const unsigned sbase = smem_u32(smem_raw);

    const int tid    = threadIdx.x;
    const int wid    = tid >> 5;
    const int lane   = tid & 31;
    const int warp_m = wid >> 1;
    const int warp_n = wid & 1;

    const char* pA = (const char*)(A + (size_t)m0 * lda + kBeg);
    const char* pB = (const char*)(B + (size_t)n0 * ldb + kBeg);

    const int nc = (kEnd - kBeg) >> 5;

    const int lr0 = tid >> 2;
    const int lcc = tid & 3;
    auto load_stage = [&](int s) {
        unsigned sb = sbase + (unsigned)(s & 1) * STAGE_B;
        const size_t kof = (size_t)s * 64 + lcc * 16;
#pragma unroll
        for (int j = 0; j < 4; j++) {
            int r = lr0 + j * 32;
            unsigned so = (unsigned)(r * 80 + lcc * 16);
            cpa16(sb + so,          pA + (size_t)r * lda * 2 + kof);
            cpa16(sb + TILE_B + so, pB + (size_t)r * ldb * 2 + kof);
        }
    };

    const unsigned aRowOff =
        (unsigned)((warp_m * 64 + (lane & 15)) * 80 + (lane >> 4) * 16);
    const unsigned bRowOff =
        (unsigned)((warp_n * 64 + (lane & 7) + (lane >> 4) * 8) * 80
                   + ((lane >> 3) & 1) * 16);

    float acc[4][8][4];
#pragma unroll
    for (int i = 0; i < 4; i++)
#pragma unroll
        for (int j = 0; j < 8; j++)
#pragma unroll
            for (int k = 0; k < 4; k++) acc[i][j][k] = 0.0f;

    load_stage(0); cpa_commit();
    if (nc > 1) load_stage(1);
    cpa_commit();

    for (int c = 0; c < nc; c++) {
        cpa_wait<1>();
        __syncthreads();

        const unsigned sb  = sbase + (unsigned)(c & 1) * STAGE_B;
        const unsigned sbB = sb + TILE_B;
#pragma unroll
        for (int ks = 0; ks < 2; ks++) {
            unsigned bh[4][4];
#pragma unroll
            for (int g = 0; g < 4; g++) {
                unsigned bd = sbB + bRowOff + g * 1280 + ks * 32;
                ldsm4(bh[g][0], bh[g][1], bh[g][2], bh[g][3], bd);
            }
#pragma unroll
            for (int mi = 0; mi < 4; mi++) {
                unsigned ah[4];
                unsigned ad = sb + aRowOff + mi * 1280 + ks * 32;
                ldsm4(ah[0], ah[1], ah[2], ah[3], ad);
#pragma unroll
                for (int ni = 0; ni < 8; ni++)
                    mma_fp(acc[mi][ni], ah,
                           bh[ni >> 1][(ni & 1) * 2], bh[ni >> 1][(ni & 1) * 2 + 1]);
            }
        }

        __syncthreads();
        if (c + 2 < nc) load_stage(c + 2);
        cpa_commit();
    }

    const int rI = lane >> 2;
    const int cI = (lane & 3) * 2;

    if (EPI == 2) {
        float* O = (float*)O0;
#pragma unroll
        for (int mi = 0; mi < 4; mi++)
#pragma unroll
            for (int ni = 0; ni < 8; ni++) {
                float* a = acc[mi][ni];
                int m = m0 + warp_m * 64 + mi * 16 + rI;
                int n = n0 + warp_n * 64 + ni * 8 + cI;
                float2 v0 = {a[0] * alpha, a[1] * alpha};
                float2 v1 = {a[2] * alpha, a[3] * alpha};
                *(float2*)(O + (size_t)m * ldo + n) = v0;
                *(float2*)(O + (size_t)(m + 8) * ldo + n) = v1;
            }
    } else if (EPI == 3) {
        __half* O = (__half*)O0;
#pragma unroll
        for (int mi = 0; mi < 4; mi++)
#pragma unroll
            for (int ni = 0; ni < 8; ni++) {
                float* a = acc[mi][ni];
                int m = m0 + warp_m * 64 + mi * 16 + rI;
                int n = n0 + warp_n * 64 + ni * 8 + cI;
                *(__half2*)(O + (size_t)m * ldo + n) =
                    __floats2half2_rn(a[0] * alpha, a[1] * alpha);
                *(__half2*)(O + (size_t)(m + 8) * ldo + n) =
                    __floats2half2_rn(a[2] * alpha, a[3] * alpha);
            }
    } else if (EPI == 6) {          // exp(alpha*acc), causal mask n > m -> 0
        __half* O = (__half*)O0;
#pragma unroll
        for (int mi = 0; mi < 4; mi++)
#pragma unroll
            for (int ni = 0; ni < 8; ni++) {
                float* a = acc[mi][ni];
                int m = m0 + warp_m * 64 + mi * 16 + rI;
                int n = n0 + warp_n * 64 + ni * 8 + cI;
                float e0 = (n     <= m) ? __expf(a[0] * alpha) : 0.0f;
                float e1 = (n + 1 <= m) ? __expf(a[1] * alpha) : 0.0f;
                *(__half2*)(O + (size_t)m * ldo + n) = __floats2half2_rn(e0, e1);
                int m8 = m + 8;
                float e2 = (n     <= m8) ? __expf(a[2] * alpha) : 0.0f;
                float e3 = (n + 1 <= m8) ? __expf(a[3] * alpha) : 0.0f;
                *(__half2*)(O + (size_t)m8 * ldo + n) = __floats2half2_rn(e2, e3);
            }
    } else {  // EPI == 5: fp16 transposed (via fp32 smem staging [128][132])
        __syncthreads();
        float* T = (float*)smem_raw;
#pragma unroll
        for (int mi = 0; mi < 4; mi++)
#pragma unroll
            for (int ni = 0; ni < 8; ni++) {
                float* a = acc[mi][ni];
                int lm = warp_m * 64 + mi * 16 + rI;
                int ln = warp_n * 64 + ni * 8 + cI;
                T[lm * 132 + ln]           = a[0];
                T[lm * 132 + ln + 1]       = a[1];
                T[(lm + 8) * 132 + ln]     = a[2];
                T[(lm + 8) * 132 + ln + 1] = a[3];
            }
        __syncthreads();
        __half* O = (__half*)O0;
        const int n = tid;
#pragma unroll
        for (int i = 0; i < 128; i += 8) {
            __half hp[8];
#pragma unroll
            for (int j = 0; j < 8; j++)
                hp[j] = __float2half_rn(T[(i + j) * 132 + n] * alpha);
            size_t o = (size_t)(n0 + n) * ldo + m0 + i;
            *(uint4*)(O + o) = *(uint4*)hp;
        }
    }
}

// ---------------------------------------------------------------------------
// Stage 0a: weight conversions only (Wq, 32*Wk, 32*Wv^T)
// ---------------------------------------------------------------------------
__global__ __launch_bounds__(256) void k_convw(
    const float* __restrict__ Wq, const float* __restrict__ Wk,
    const float* __restrict__ Wv)
{
    __shared__ float t[32][33];
    const int b = blockIdx.x;
    const int tid = threadIdx.x;
    if (b < 1024) {
        size_t i = ((size_t)b * 256 + tid) * 4;
        float4 v = *(const float4*)(Wq + i);
        *(__half2*)(g_wq + i)     = __floats2half2_rn(v.x, v.y);
        *(__half2*)(g_wq + i + 2) = __floats2half2_rn(v.z, v.w);
    } else if (b < 2048) {
        size_t i = ((size_t)(b - 1024) * 256 + tid) * 4;
        float4 v = *(const float4*)(Wk + i);
        *(__half2*)(g_wk32 + i)     = __floats2half2_rn(v.x * 32.f, v.y * 32.f);
        *(__half2*)(g_wk32 + i + 2) = __floats2half2_rn(v.z * 32.f, v.w * 32.f);
    } else {
        const int u  = b - 2048;
        const int h0 = (u & 31) * 32, d0 = (u >> 5) * 32;
        const int tx = tid & 31, ty = tid >> 5;
        for (int i = ty; i < 32; i += 8)
            t[i][tx] = Wv[(size_t)(d0 + i) * H + h0 + tx];
        __syncthreads();
        for (int i = ty; i < 32; i += 8)
            g_wvt[(size_t)(h0 + i) * D + d0 + tx] = __float2half_rn(t[tx][i] * 32.f);
    }
}

// ---------------------------------------------------------------------------
// Stage 0b: G = 32*Wk @ Wq^T, split-K4 -> fp32 partials in g_s
// ---------------------------------------------------------------------------
__global__ __launch_bounds__(NT, 2) void k_g()
{
    const int gm = blockIdx.y >> 2;
    const int j  = blockIdx.y & 3;
    float* O = (float*)g_s + (size_t)j * (D * D);
    gemm128<2>(g_wk32, H, g_wq, H, (void*)O, D, 1.0f,
               gm * 128, blockIdx.x * 128, j * 256, j * 256 + 256);
}

// ---------------------------------------------------------------------------
// Stage 0c: x -> fp16
// ---------------------------------------------------------------------------
__global__ __launch_bounds__(256) void k_convx(const float* __restrict__ x)
{
    size_t i = ((size_t)blockIdx.x * 256 + threadIdx.x) * 4;
    float4 v = *(const float4*)(x + i);
    *(__half2*)(g_x + i)     = __floats2half2_rn(v.x, v.y);
    *(__half2*)(g_x + i + 2) = __floats2half2_rn(v.z, v.w);
}

// ---------------------------------------------------------------------------
// Stage 0d: reduce 4 G partials -> g_g fp16
// ---------------------------------------------------------------------------
__global__ __launch_bounds__(256) void k_gred()
{
    size_t i = ((size_t)blockIdx.x * 256 + threadIdx.x) * 4;
    const float* s = (const float*)g_s;
    float4 a = *(const float4*)(s + i);
    float4 b = *(const float4*)(s + (size_t)D * D + i);
    float4 c = *(const float4*)(s + (size_t)2 * D * D + i);
    float4 d = *(const float4*)(s + (size_t)3 * D * D + i);
    *(__half2*)(g_g + i)     = __floats2half2_rn(a.x + b.x + c.x + d.x,
                                                 a.y + b.y + c.y + d.y);
    *(__half2*)(g_g + i + 2) = __floats2half2_rn(a.z + b.z + c.z + d.z,
                                                 a.w + b.w + c.w + d.w);
}

// ---------------------------------------------------------------------------
// Stage 1: merged v^T and t (uniform 32-chunk CTAs, 512 total):
//   y < 32 : v^T = (x @ 32Wv)^T / 32  (EPI5)
//   y >= 32: t = x (x) G              (EPI3)
// ---------------------------------------------------------------------------
__global__ __launch_bounds__(NT, 2) void k_vt()
{
    const int by = blockIdx.y, bx = blockIdx.x;
    if (by < 32) {
        gemm128<5>(g_x, D, g_wvt, D, (void*)g_vt, L, 0.03125f,
                   by * 128, bx * 128, 0, D);
    } else {
        gemm128<3>(g_x, D, g_g, D, (void*)g_t, D, 1.0f,
                   (by - 32) * 128, bx * 128, 0, D);
    }
}

// ---------------------------------------------------------------------------
// Stage 2: P' = exp(t.x^T / 1024) with causal mask.
// 1-D triangular grid: exactly 528 CTAs, u -> (by, bx) with bx <= by.
// ---------------------------------------------------------------------------
__global__ __launch_bounds__(NT, 2) void k_scores()
{
    const int u = blockIdx.x;
    int by = (int)((__fsqrt_rn(8.0f * (float)u + 1.0f) - 1.0f) * 0.5f);
    while ((by + 1) * (by + 2) / 2 <= u) by++;
    while (by * (by + 1) / 2 > u)        by--;
    const int bx = u - by * (by + 1) / 2;
    gemm128<6>(g_t, D, g_x, D, (void*)g_p, L, 1.0f / 1024.0f,
               by * 128, bx * 128, 0, D);
}

// ---------------------------------------------------------------------------
// Stage 3: out = P' @ v (unnormalized), balanced split-K (pieces <= 32 chunks)
// np(bi)=bi/8+1; long pieces first. j=0 -> out; j>=1 -> scratch slots in g_s.
// ---------------------------------------------------------------------------
__global__ __launch_bounds__(NT, 2) void k_pv(float* __restrict__ out)
{
    const int y = blockIdx.y, x = blockIdx.x;
    int bi, j, np;
    if (y < 32)      { bi = 31 - (y >> 2);        j = y & 3;          np = 4; }
    else if (y < 56) { int u = y - 32; bi = 23 - u / 3; j = u % 3;    np = 3; }
    else if (y < 72) { int u = y - 56; bi = 15 - (u >> 1); j = u & 1; np = 2; }
    else             { bi = 7 - (y - 72);         j = 0;              np = 1; }

    const int Kc = (bi + 1) * 4;
    const int kb = (j * Kc) / np * 32;
    const int ke = ((j + 1) * Kc) / np * 32;
    const int m0 = bi * 128, n0 = x * 128;

    if (j == 0) {
        gemm128<2>(g_p, L, g_vt, L, (void*)out, H, 1.0f, m0, n0, kb, ke);
    } else {
        int sl;
        if (bi < 16)      sl = bi - 8;
        else if (bi < 24) sl = 8 + (bi - 16) * 2 + (j - 1);
        else              sl = 24 + (bi - 24) * 3 + (j - 1);
        float* base = (float*)g_s + (size_t)(sl * 8 + x) * 16384;
        float* O = base - (size_t)m0 * 128 - n0;
        gemm128<2>(g_p, L, g_vt, L, (void*)O, 128, 1.0f, m0, n0, kb, ke);
    }
}

// ---------------------------------------------------------------------------
// Stage 4: one block per output row m: rowsum(P'[m]) -> inv, merge split-K
// partials, scale. (fused rowsum + pvscale)
// ---------------------------------------------------------------------------
__global__ __launch_bounds__(256) void k_pvscale(float* __restrict__ out)
{
    __shared__ float red[256];
    const int m   = blockIdx.x;
    const int tid = threadIdx.x;
    const int end = ((m >> 7) + 1) << 7;

    const __half* p = g_p + (size_t)m * L;
    float acc = 0.0f;
    for (int i = tid * 2; i < end; i += 512) {
        __half2 v = *(const __half2*)(p + i);
        float2 f = __half22float2(v);
        acc += f.x + f.y;
    }
    red[tid] = acc;
    __syncthreads();
    for (int s = 128; s > 0; s >>= 1) {
        if (tid < s) red[tid] += red[tid + s];
        __syncthreads();
    }
    const float inv = 1.0f / red[0];

    const int n  = tid * 4;
    const int bi = m >> 7;
    const int np = (bi >> 3) + 1;
    size_t oi = (size_t)m * H + n;

    float4 a = *(float4*)(out + oi);
    if (np > 1) {
        const int r128 = m & 127;
        const int xt = n >> 7;
        const int nl = n & 127;
        const float* s = (const float*)g_s;
#pragma unroll 3
        for (int j = 1; j < 4; j++) {
            if (j >= np) break;
            int sl;
            if (bi < 16)      sl = bi - 8;
            else if (bi < 24) sl = 8 + (bi - 16) * 2 + (j - 1);
            else              sl = 24 + (bi - 24) * 3 + (j - 1);
            const float* b = s + (size_t)(sl * 8 + xt) * 16384 + r128 * 128 + nl;
            float4 v = *(const float4*)b;
            a.x += v.x; a.y += v.y; a.z += v.z; a.w += v.w;
        }
    }
    a.x *= inv; a.y *= inv; a.z *= inv; a.w *= inv;
    *(float4*)(out + oi) = a;
}

// ---------------------------------------------------------------------------
extern "C" void kernel_launch(void* const* d_in, const int* in_sizes, int n_in,
                              void* d_out, int out_size)
{
    const float* x  = (const float*)d_in[0];
    // d_in[1] = mask (structurally triu(k=1); causality handled directly)
    const float* Wq = (const float*)d_in[2];
    const float* Wk = (const float*)d_in[3];
    const float* Wv = (const float*)d_in[4];
    float* out = (float*)d_out;

    cudaFuncSetAttribute(k_vt, cudaFuncAttributeMaxDynamicSharedMemorySize, SMEM_QKV);

    k_convw<<<3072, 256>>>(Wq, Wk, Wv);
    k_g<<<dim3(8, 32), NT, SMEM_G>>>();
    k_convx<<<(L * D) / 1024, 256>>>(x);
    k_gred<<<(D * D) / 1024, 256>>>();
    k_vt<<<dim3(8, 64), NT, SMEM_QKV>>>();
    k_scores<<<528, NT, SMEM_G>>>();
    k_pv<<<dim3(8, 80), NT, SMEM_G>>>(out);
    k_pvscale<<<L, 256>>>(out);
}

// round 15
// speedup vs baseline: 1.0818x; 1.0107x over previous
#include <cuda_runtime.h>
#include <cuda_fp16.h>

#define L 4096
#define D 1024
#define H 1024

// ---------------------------------------------------------------------------
// Scratch (__device__ globals; allocation-free rule)
// ---------------------------------------------------------------------------
__device__ __half g_x[(size_t)L * D];        // x fp16
__device__ __half g_wq[(size_t)D * H];       // Wq fp16         [d, h]
__device__ __half g_wk32[(size_t)D * H];     // 32*Wk fp16      [e, h]
__device__ __half g_wvt[(size_t)H * D];      // 32*Wv^T fp16    [h, d]
__device__ __half g_g[(size_t)D * D];        // G = 32*Wk.Wq^T  [e, d]
__device__ __half g_t[(size_t)L * D];        // t = x.G^T       [l, e]
__device__ __half g_vt[(size_t)H * L];       // v^T fp16        [h, l]
__device__ float  g_s[(size_t)L * L];        // G partials / pv partials
__device__ __half g_p[(size_t)L * L];        // P' = exp(S) fp16 (unnormalized)
__device__ float  g_rsum[L];                 // rowsum(P') via epilogue atomics

// ---------------------------------------------------------------------------
// Helpers
// ---------------------------------------------------------------------------
__device__ __forceinline__ unsigned smem_u32(const void* p) {
    unsigned a;
    asm("{ .reg .u64 t; cvta.to.shared.u64 t, %1; cvt.u32.u64 %0, t; }"
        : "=r"(a) : "l"(p));
    return a;
}
__device__ __forceinline__ void cpa16(unsigned dst, const void* src) {
    asm volatile("cp.async.cg.shared.global [%0], [%1], 16;"
                 :: "r"(dst), "l"(src) : "memory");
}
__device__ __forceinline__ void cpa_commit() {
    asm volatile("cp.async.commit_group;" ::: "memory");
}
template <int N>
__device__ __forceinline__ void cpa_wait() {
    asm volatile("cp.async.wait_group %0;" :: "n"(N) : "memory");
}
__device__ __forceinline__ void ldsm4(unsigned& r0, unsigned& r1, unsigned& r2,
                                      unsigned& r3, unsigned addr) {
    asm volatile("ldmatrix.sync.aligned.m8n8.x4.shared.b16 {%0,%1,%2,%3}, [%4];"
                 : "=r"(r0), "=r"(r1), "=r"(r2), "=r"(r3) : "r"(addr));
}
__device__ __forceinline__ void mma_fp(float* c, const unsigned* a,
                                       unsigned b0, unsigned b1) {
    asm volatile(
        "mma.sync.aligned.m16n8k16.row.col.f32.f16.f16.f32 "
        "{%0,%1,%2,%3}, {%4,%5,%6,%7}, {%8,%9}, {%0,%1,%2,%3};"
        : "+f"(c[0]), "+f"(c[1]), "+f"(c[2]), "+f"(c[3])
        : "r"(a[0]), "r"(a[1]), "r"(a[2]), "r"(a[3]), "r"(b0), "r"(b1));
}

// ---------------------------------------------------------------------------
// Single-fp16 128x128 GEMM-NT (R11-proven engine — FROZEN):
// C = alpha*(A @ B^T), K range [kBeg, kEnd). 128 threads, 4 warps (2x2),
// warp tile 64x64; pad-80 smem rows; BK=32; 2-stage cp.async
// load-after-compute; 2 CTAs/SM.
// EPI: 2 = fp32*alpha row-major | 3 = fp16*alpha row-major
//      5 = fp16*alpha TRANSPOSED
//      6 = fp16 exp(alpha*acc) causal-masked + rowsum atomics into g_rsum
// ---------------------------------------------------------------------------
#define TILE_B    10240            // 128 rows x 40 halves (pad)
#define STAGE_B   (2 * TILE_B)
#define NT        128
#define SMEM_G    (2 * STAGE_B)    // 40960
#define SMEM_QKV  67584            // [128][132] fp32 transpose staging

template <int EPI>
__device__ __forceinline__ void gemm128(
    const __half* __restrict__ A, int lda,
    const __half* __restrict__ B, int ldb,
    void* O0, int ldo, float alpha,
    int m0, int n0, int kBeg, int kEnd)
{
    extern __shared__ char smem_raw[];
    const unsigned sbase = smem_u32(smem_raw);

    const int tid    = threadIdx.x;
    const int wid    = tid >> 5;
    const int lane   = tid & 31;
    const int warp_m = wid >> 1;
    const int warp_n = wid & 1;

    const char* pA = (const char*)(A + (size_t)m0 * lda + kBeg);
    const char* pB = (const char*)(B + (size_t)n0 * ldb + kBeg);

    const int nc = (kEnd - kBeg) >> 5;

    const int lr0 = tid >> 2;
    const int lcc = tid & 3;
    auto load_stage = [&](int s) {
        unsigned sb = sbase + (unsigned)(s & 1) * STAGE_B;
        const size_t kof = (size_t)s * 64 + lcc * 16;
#pragma unroll
        for (int j = 0; j < 4; j++) {
            int r = lr0 + j * 32;
            unsigned so = (unsigned)(r * 80 + lcc * 16);
            cpa16(sb + so,          pA + (size_t)r * lda * 2 + kof);
            cpa16(sb + TILE_B + so, pB + (size_t)r * ldb * 2 + kof);
        }
    };

    const unsigned aRowOff =
        (unsigned)((warp_m * 64 + (lane & 15)) * 80 + (lane >> 4) * 16);
    const unsigned bRowOff =
        (unsigned)((warp_n * 64 + (lane & 7) + (lane >> 4) * 8) * 80
                   + ((lane >> 3) & 1) * 16);

    float acc[4][8][4];
#pragma unroll
    for (int i = 0; i < 4; i++)
#pragma unroll
        for (int j = 0; j < 8; j++)
#pragma unroll
            for (int k = 0; k < 4; k++) acc[i][j][k] = 0.0f;

    load_stage(0); cpa_commit();
    if (nc > 1) load_stage(1);
    cpa_commit();

    for (int c = 0; c < nc; c++) {
        cpa_wait<1>();
        __syncthreads();

        const unsigned sb  = sbase + (unsigned)(c & 1) * STAGE_B;
        const unsigned sbB = sb + TILE_B;
#pragma unroll
        for (int ks = 0; ks < 2; ks++) {
            unsigned bh[4][4];
#pragma unroll
            for (int g = 0; g < 4; g++) {
                unsigned bd = sbB + bRowOff + g * 1280 + ks * 32;
                ldsm4(bh[g][0], bh[g][1], bh[g][2], bh[g][3], bd);
            }
#pragma unroll
            for (int mi = 0; mi < 4; mi++) {
                unsigned ah[4];
                unsigned ad = sb + aRowOff + mi * 1280 + ks * 32;
                ldsm4(ah[0], ah[1], ah[2], ah[3], ad);
#pragma unroll
                for (int ni = 0; ni < 8; ni++)
                    mma_fp(acc[mi][ni], ah,
                           bh[ni >> 1][(ni & 1) * 2], bh[ni >> 1][(ni & 1) * 2 + 1]);
            }
        }

        __syncthreads();
        if (c + 2 < nc) load_stage(c + 2);
        cpa_commit();
    }

    const int rI = lane >> 2;
    const int cI = (lane & 3) * 2;

    if (EPI == 2) {
        float* O = (float*)O0;
#pragma unroll
        for (int mi = 0; mi < 4; mi++)
#pragma unroll
            for (int ni = 0; ni < 8; ni++) {
                float* a = acc[mi][ni];
                int m = m0 + warp_m * 64 + mi * 16 + rI;
                int n = n0 + warp_n * 64 + ni * 8 + cI;
                float2 v0 = {a[0] * alpha, a[1] * alpha};
                float2 v1 = {a[2] * alpha, a[3] * alpha};
                *(float2*)(O + (size_t)m * ldo + n) = v0;
                *(float2*)(O + (size_t)(m + 8) * ldo + n) = v1;
            }
    } else if (EPI == 3) {
        __half* O = (__half*)O0;
#pragma unroll
        for (int mi = 0; mi < 4; mi++)
#pragma unroll
            for (int ni = 0; ni < 8; ni++) {
                float* a = acc[mi][ni];
                int m = m0 + warp_m * 64 + mi * 16 + rI;
                int n = n0 + warp_n * 64 + ni * 8 + cI;
                *(__half2*)(O + (size_t)m * ldo + n) =
                    __floats2half2_rn(a[0] * alpha, a[1] * alpha);
                *(__half2*)(O + (size_t)(m + 8) * ldo + n) =
                    __floats2half2_rn(a[2] * alpha, a[3] * alpha);
            }
    } else if (EPI == 6) {  // exp(alpha*acc), causal mask, + rowsum atomics
        __half* O = (__half*)O0;
        float rs[4][2];
#pragma unroll
        for (int mi = 0; mi < 4; mi++) { rs[mi][0] = 0.0f; rs[mi][1] = 0.0f; }
#pragma unroll
        for (int mi = 0; mi < 4; mi++)
#pragma unroll
            for (int ni = 0; ni < 8; ni++) {
                float* a = acc[mi][ni];
                int m = m0 + warp_m * 64 + mi * 16 + rI;
                int n = n0 + warp_n * 64 + ni * 8 + cI;
                float e0 = (n     <= m) ? __expf(a[0] * alpha) : 0.0f;
                float e1 = (n + 1 <= m) ? __expf(a[1] * alpha) : 0.0f;
                *(__half2*)(O + (size_t)m * ldo + n) = __floats2half2_rn(e0, e1);
                int m8 = m + 8;
                float e2 = (n     <= m8) ? __expf(a[2] * alpha) : 0.0f;
                float e3 = (n + 1 <= m8) ? __expf(a[3] * alpha) : 0.0f;
                *(__half2*)(O + (size_t)m8 * ldo + n) = __floats2half2_rn(e2, e3);
                rs[mi][0] += e0 + e1;
                rs[mi][1] += e2 + e3;
            }
        // 4 lanes (same rI, cI groups) hold partial sums of each row
#pragma unroll
        for (int mi = 0; mi < 4; mi++)
#pragma unroll
            for (int r = 0; r < 2; r++) {
                float v = rs[mi][r];
                v += __shfl_xor_sync(0xFFFFFFFFu, v, 1);
                v += __shfl_xor_sync(0xFFFFFFFFu, v, 2);
                if ((lane & 3) == 0)
                    atomicAdd(&g_rsum[m0 + warp_m * 64 + mi * 16 + rI + r * 8], v);
            }
    } else {  // EPI == 5: fp16 transposed (via fp32 smem staging [128][132])
        __syncthreads();
        float* T = (float*)smem_raw;
#pragma unroll
        for (int mi = 0; mi < 4; mi++)
#pragma unroll
            for (int ni = 0; ni < 8; ni++) {
                float* a = acc[mi][ni];
                int lm = warp_m * 64 + mi * 16 + rI;
                int ln = warp_n * 64 + ni * 8 + cI;
                T[lm * 132 + ln]           = a[0];
                T[lm * 132 + ln + 1]       = a[1];
                T[(lm + 8) * 132 + ln]     = a[2];
                T[(lm + 8) * 132 + ln + 1] = a[3];
            }
        __syncthreads();
        __half* O = (__half*)O0;
        const int n = tid;
#pragma unroll
        for (int i = 0; i < 128; i += 8) {
            __half hp[8];
#pragma unroll
            for (int j = 0; j < 8; j++)
                hp[j] = __float2half_rn(T[(i + j) * 132 + n] * alpha);
            size_t o = (size_t)(n0 + n) * ldo + m0 + i;
            *(uint4*)(O + o) = *(uint4*)hp;
        }
    }
}

// ---------------------------------------------------------------------------
// Stage 0: all input conversions in one launch.
// ---------------------------------------------------------------------------
__global__ __launch_bounds__(256) void k_conv(
    const float* __restrict__ x,  const float* __restrict__ Wq,
    const float* __restrict__ Wk, const float* __restrict__ Wv)
{
    __shared__ float t[32][33];
    const int b = blockIdx.x;
    const int tid = threadIdx.x;
    if (b < 4096) {
        size_t i = ((size_t)b * 256 + tid) * 4;
        float4 v = *(const float4*)(x + i);
        *(__half2*)(g_x + i)     = __floats2half2_rn(v.x, v.y);
        *(__half2*)(g_x + i + 2) = __floats2half2_rn(v.z, v.w);
    } else if (b < 5120) {
        size_t i = ((size_t)(b - 4096) * 256 + tid) * 4;
        float4 v = *(const float4*)(Wq + i);
        *(__half2*)(g_wq + i)     = __floats2half2_rn(v.x, v.y);
        *(__half2*)(g_wq + i + 2) = __floats2half2_rn(v.z, v.w);
    } else if (b < 6144) {
        size_t i = ((size_t)(b - 5120) * 256 + tid) * 4;
        float4 v = *(const float4*)(Wk + i);
        *(__half2*)(g_wk32 + i)     = __floats2half2_rn(v.x * 32.f, v.y * 32.f);
        *(__half2*)(g_wk32 + i + 2) = __floats2half2_rn(v.z * 32.f, v.w * 32.f);
    } else {
        const int u  = b - 6144;
        const int h0 = (u & 31) * 32, d0 = (u >> 5) * 32;
        const int tx = tid & 31, ty = tid >> 5;
        for (int i = ty; i < 32; i += 8)
            t[i][tx] = Wv[(size_t)(d0 + i) * H + h0 + tx];
        __syncthreads();
        for (int i = ty; i < 32; i += 8)
            g_wvt[(size_t)(h0 + i) * D + d0 + tx] = __float2half_rn(t[tx][i] * 32.f);
    }
}

// ---------------------------------------------------------------------------
// Stage 1: G = 32*Wk @ Wq^T, split-K4 -> fp32 partials in g_s
// ---------------------------------------------------------------------------
__global__ __launch_bounds__(NT, 2) void k_g()
{
    const int gm = blockIdx.y >> 2;
    const int j  = blockIdx.y & 3;
    float* O = (float*)g_s + (size_t)j * (D * D);
    gemm128<2>(g_wk32, H, g_wq, H, (void*)O, D, 1.0f,
               gm * 128, blockIdx.x * 128, j * 256, j * 256 + 256);
}

// ---------------------------------------------------------------------------
// Stage 2: reduce 4 G partials -> g_g fp16 (2 float4/stream/thread for MLP);
// block 0 also zeroes g_rsum for the scores-epilogue atomics.
// ---------------------------------------------------------------------------
__global__ __launch_bounds__(256) void k_gred()
{
    if (blockIdx.x == 0) {
#pragma unroll
        for (int j = 0; j < 16; j++) g_rsum[threadIdx.x * 16 + j] = 0.0f;
    }
    const float* s = (const float*)g_s;
#pragma unroll
    for (int u = 0; u < 2; u++) {
        size_t i = (((size_t)blockIdx.x * 512) + threadIdx.x * 2 + u) * 4;
        float4 a = *(const float4*)(s + i);
        float4 b = *(const float4*)(s + (size_t)D * D + i);
        float4 c = *(const float4*)(s + (size_t)2 * D * D + i);
        float4 d = *(const float4*)(s + (size_t)3 * D * D + i);
        *(__half2*)(g_g + i)     = __floats2half2_rn(a.x + b.x + c.x + d.x,
                                                     a.y + b.y + c.y + d.y);
        *(__half2*)(g_g + i + 2) = __floats2half2_rn(a.z + b.z + c.z + d.z,
                                                     a.w + b.w + c.w + d.w);
    }
}

// ---------------------------------------------------------------------------
// Stage 3: merged v^T and t (uniform 32-chunk CTAs, 512 total)
// ---------------------------------------------------------------------------
__global__ __launch_bounds__(NT, 2) void k_vt()
{
    const int by = blockIdx.y, bx = blockIdx.x;
    if (by < 32) {
        gemm128<5>(g_x, D, g_wvt, D, (void*)g_vt, L, 0.03125f,
                   by * 128, bx * 128, 0, D);
    } else {
        gemm128<3>(g_x, D, g_g, D, (void*)g_t, D, 1.0f,
                   (by - 32) * 128, bx * 128, 0, D);
    }
}

// ---------------------------------------------------------------------------
// Stage 4: P' = exp(t.x^T / 1024), causal mask, + rowsum atomics.
// 1-D triangular grid: exactly 528 CTAs.
// ---------------------------------------------------------------------------
__global__ __launch_bounds__(NT, 2) void k_scores()
{
    const int u = blockIdx.x;
    int by = (int)((__fsqrt_rn(8.0f * (float)u + 1.0f) - 1.0f) * 0.5f);
    while ((by + 1) * (by + 2) / 2 <= u) by++;
    while (by * (by + 1) / 2 > u)        by--;
    const int bx = u - by * (by + 1) / 2;
    gemm128<6>(g_t, D, g_x, D, (void*)g_p, L, 1.0f / 1024.0f,
               by * 128, bx * 128, 0, D);
}

// ---------------------------------------------------------------------------
// Stage 5: out = P' @ v (unnormalized), balanced split-K (pieces <= 32 chunks)
// ---------------------------------------------------------------------------
__global__ __launch_bounds__(NT, 2) void k_pv(float* __restrict__ out)
{
    const int y = blockIdx.y, x = blockIdx.x;
    int bi, j, np;
    if (y < 32)      { bi = 31 - (y >> 2);        j = y & 3;          np = 4; }
    else if (y < 56) { int u = y - 32; bi = 23 - u / 3; j = u % 3;    np = 3; }
    else if (y < 72) { int u = y - 56; bi = 15 - (u >> 1); j = u & 1; np = 2; }
    else             { bi = 7 - (y - 72);         j = 0;              np = 1; }

    const int Kc = (bi + 1) * 4;
    const int kb = (j * Kc) / np * 32;
    const int ke = ((j + 1) * Kc) / np * 32;
    const int m0 = bi * 128, n0 = x * 128;

    if (j == 0) {
        gemm128<2>(g_p, L, g_vt, L, (void*)out, H, 1.0f, m0, n0, kb, ke);
    } else {
        int sl;
        if (bi < 16)      sl = bi - 8;
        else if (bi < 24) sl = 8 + (bi - 16) * 2 + (j - 1);
        else              sl = 24 + (bi - 24) * 3 + (j - 1);
        float* base = (float*)g_s + (size_t)(sl * 8 + x) * 16384;
        float* O = base - (size_t)m0 * 128 - n0;
        gemm128<2>(g_p, L, g_vt, L, (void*)O, 128, 1.0f, m0, n0, kb, ke);
    }
}

// ---------------------------------------------------------------------------
// Stage 6: one block per output row m: merge split-K partials, scale by
// 1/g_rsum[m] (sums already accumulated by the scores epilogue).
// ---------------------------------------------------------------------------
__global__ __launch_bounds__(256) void k_pvscale(float* __restrict__ out)
{
    const int m   = blockIdx.x;
    const int tid = threadIdx.x;
    const float inv = 1.0f / g_rsum[m];

    const int n  = tid * 4;
    const int bi = m >> 7;
    const int np = (bi >> 3) + 1;
    size_t oi = (size_t)m * H + n;

    float4 a = *(float4*)(out + oi);
    if (np > 1) {
        const int r128 = m & 127;
        const int xt = n >> 7;
        const int nl = n & 127;
        const float* s = (const float*)g_s;
#pragma unroll 3
        for (int j = 1; j < 4; j++) {
            if (j >= np) break;
            int sl;
            if (bi < 16)      sl = bi - 8;
            else if (bi < 24) sl = 8 + (bi - 16) * 2 + (j - 1);
            else              sl = 24 + (bi - 24) * 3 + (j - 1);
            const float* b = s + (size_t)(sl * 8 + xt) * 16384 + r128 * 128 + nl;
            float4 v = *(const float4*)b;
            a.x += v.x; a.y += v.y; a.z += v.z; a.w += v.w;
        }
    }
    a.x *= inv; a.y *= inv; a.z *= inv; a.w *= inv;
    *(float4*)(out + oi) = a;
}

// ---------------------------------------------------------------------------
extern "C" void kernel_launch(void* const* d_in, const int* in_sizes, int n_in,
                              void* d_out, int out_size)
{
    const float* x  = (const float*)d_in[0];
    // d_in[1] = mask (structurally triu(k=1); causality handled directly)
    const float* Wq = (const float*)d_in[2];
    const float* Wk = (const float*)d_in[3];
    const float* Wv = (const float*)d_in[4];
    float* out = (float*)d_out;

    cudaFuncSetAttribute(k_vt, cudaFuncAttributeMaxDynamicSharedMemorySize, SMEM_QKV);

    k_conv<<<7168, 256>>>(x, Wq, Wk, Wv);
    k_g<<<dim3(8, 32), NT, SMEM_G>>>();
    k_gred<<<512, 256>>>();
    k_vt<<<dim3(8, 64), NT, SMEM_QKV>>>();
    k_scores<<<528, NT, SMEM_G>>>();
    k_pv<<<dim3(8, 80), NT, SMEM_G>>>(out);
    k_pvscale<<<L, 256>>>(out);
}

// round 16
// speedup vs baseline: 1.0867x; 1.0046x over previous
#include <cuda_runtime.h>
#include <cuda_fp16.h>

#define L 4096
#define D 1024
#define H 1024

// ---------------------------------------------------------------------------
// Scratch (__device__ globals; allocation-free rule)
// ---------------------------------------------------------------------------
__device__ __half g_x[(size_t)L * D];        // x fp16
__device__ __half g_wq[(size_t)D * H];       // Wq fp16         [d, h]
__device__ __half g_wk32[(size_t)D * H];     // 32*Wk fp16      [e, h]
__device__ __half g_wvt[(size_t)H * D];      // 32*Wv^T fp16    [h, d]
__device__ __half g_g[(size_t)D * D];        // G = 32*Wk.Wq^T  [e, d]
__device__ __half g_t[(size_t)L * D];        // t = x.G^T       [l, e]
__device__ __half g_vt[(size_t)H * L];       // v^T fp16        [h, l]
__device__ float  g_s[(size_t)L * L];        // G partials / pv partials
__device__ __half g_p[(size_t)L * L];        // P' = exp(S) fp16 (unnormalized)
__device__ float  g_rsum[L];                 // rowsum(P') via epilogue atomics

// ---------------------------------------------------------------------------
// Helpers
// ---------------------------------------------------------------------------
__device__ __forceinline__ unsigned smem_u32(const void* p) {
    unsigned a;
    asm("{ .reg .u64 t; cvta.to.shared.u64 t, %1; cvt.u32.u64 %0, t; }"
        : "=r"(a) : "l"(p));
    return a;
}
__device__ __forceinline__ void cpa16(unsigned dst, const void* src) {
    asm volatile("cp.async.cg.shared.global [%0], [%1], 16;"
                 :: "r"(dst), "l"(src) : "memory");
}
__device__ __forceinline__ void cpa_commit() {
    asm volatile("cp.async.commit_group;" ::: "memory");
}
template <int N>
__device__ __forceinline__ void cpa_wait() {
    asm volatile("cp.async.wait_group %0;" :: "n"(N) : "memory");
}
__device__ __forceinline__ void ldsm4(unsigned& r0, unsigned& r1, unsigned& r2,
                                      unsigned& r3, unsigned addr) {
    asm volatile("ldmatrix.sync.aligned.m8n8.x4.shared.b16 {%0,%1,%2,%3}, [%4];"
                 : "=r"(r0), "=r"(r1), "=r"(r2), "=r"(r3) : "r"(addr));
}
__device__ __forceinline__ void mma_fp(float* c, const unsigned* a,
                                       unsigned b0, unsigned b1) {
    asm volatile(
        "mma.sync.aligned.m16n8k16.row.col.f32.f16.f16.f32 "
        "{%0,%1,%2,%3}, {%4,%5,%6,%7}, {%8,%9}, {%0,%1,%2,%3};"
        : "+f"(c[0]), "+f"(c[1]), "+f"(c[2]), "+f"(c[3])
        : "r"(a[0]), "r"(a[1]), "r"(a[2]), "r"(a[3]), "r"(b0), "r"(b1));
}

// ---------------------------------------------------------------------------
// Single-fp16 128x128 GEMM-NT (R11-proven engine — FROZEN):
// C = alpha*(A @ B^T), K range [kBeg, kEnd). 128 threads, 4 warps (2x2),
// warp tile 64x64; pad-80 smem rows; BK=32; 2-stage cp.async
// load-after-compute; 2 CTAs/SM.
// EPI: 2 = fp32*alpha row-major | 3 = fp16*alpha row-major
//      5 = fp16*alpha TRANSPOSED
//      6 = fp16 exp(alpha*acc) causal-masked + rowsum atomics into g_rsum
// ---------------------------------------------------------------------------
#define TILE_B    10240            // 128 rows x 40 halves (pad)
#define STAGE_B   (2 * TILE_B)
#define NT        128
#define SMEM_G    (2 * STAGE_B)    // 40960
#define SMEM_QKV  67584            // [128][132] fp32 transpose staging

template <int EPI>
__device__ __forceinline__ void gemm128(
    const __half* __restrict__ A, int lda,
    const __half* __restrict__ B, int ldb,
    void* O0, int ldo, float alpha,
    int m0, int n0, int kBeg, int kEnd)
{
    extern __shared__ char smem_raw[];
    const unsigned sbase = smem_u32(smem_raw);

    const int tid    = threadIdx.x;
    const int wid    = tid >> 5;
    const int lane   = tid & 31;
    const int warp_m = wid >> 1;
    const int warp_n = wid & 1;

    const char* pA = (const char*)(A + (size_t)m0 * lda + kBeg);
    const char* pB = (const char*)(B + (size_t)n0 * ldb + kBeg);

    const int nc = (kEnd - kBeg) >> 5;

    const int lr0 = tid >> 2;
    const int lcc = tid & 3;
    auto load_stage = [&](int s) {
        unsigned sb = sbase + (unsigned)(s & 1) * STAGE_B;
        const size_t kof = (size_t)s * 64 + lcc * 16;
#pragma unroll
        for (int j = 0; j < 4; j++) {
            int r = lr0 + j * 32;
            unsigned so = (unsigned)(r * 80 + lcc * 16);
            cpa16(sb + so,          pA + (size_t)r * lda * 2 + kof);
            cpa16(sb + TILE_B + so, pB + (size_t)r * ldb * 2 + kof);
        }
    };

    const unsigned aRowOff =
        (unsigned)((warp_m * 64 + (lane & 15)) * 80 + (lane >> 4) * 16);
    const unsigned bRowOff =
        (unsigned)((warp_n * 64 + (lane & 7) + (lane >> 4) * 8) * 80
                   + ((lane >> 3) & 1) * 16);

    float acc[4][8][4];
#pragma unroll
    for (int i = 0; i < 4; i++)
#pragma unroll
        for (int j = 0; j < 8; j++)
#pragma unroll
            for (int k = 0; k < 4; k++) acc[i][j][k] = 0.0f;

    load_stage(0); cpa_commit();
    if (nc > 1) load_stage(1);
    cpa_commit();

    for (int c = 0; c < nc; c++) {
        cpa_wait<1>();
        __syncthreads();

        const unsigned sb  = sbase + (unsigned)(c & 1) * STAGE_B;
        const unsigned sbB = sb + TILE_B;
#pragma unroll
        for (int ks = 0; ks < 2; ks++) {
            unsigned bh[4][4];
#pragma unroll
            for (int g = 0; g < 4; g++) {
                unsigned bd = sbB + bRowOff + g * 1280 + ks * 32;
                ldsm4(bh[g][0], bh[g][1], bh[g][2], bh[g][3], bd);
            }
#pragma unroll
            for (int mi = 0; mi < 4; mi++) {
                unsigned ah[4];
                unsigned ad = sb + aRowOff + mi * 1280 + ks * 32;
                ldsm4(ah[0], ah[1], ah[2], ah[3], ad);
#pragma unroll
                for (int ni = 0; ni < 8; ni++)
                    mma_fp(acc[mi][ni], ah,
                           bh[ni >> 1][(ni & 1) * 2], bh[ni >> 1][(ni & 1) * 2 + 1]);
            }
        }

        __syncthreads();
        if (c + 2 < nc) load_stage(c + 2);
        cpa_commit();
    }

    const int rI = lane >> 2;
    const int cI = (lane & 3) * 2;

    if (EPI == 2) {
        float* O = (float*)O0;
#pragma unroll
        for (int mi = 0; mi < 4; mi++)
#pragma unroll
            for (int ni = 0; ni < 8; ni++) {
                float* a = acc[mi][ni];
                int m = m0 + warp_m * 64 + mi * 16 + rI;
                int n = n0 + warp_n * 64 + ni * 8 + cI;
                float2 v0 = {a[0] * alpha, a[1] * alpha};
                float2 v1 = {a[2] * alpha, a[3] * alpha};
                *(float2*)(O + (size_t)m * ldo + n) = v0;
                *(float2*)(O + (size_t)(m + 8) * ldo + n) = v1;
            }
    } else if (EPI == 3) {
        __half* O = (__half*)O0;
#pragma unroll
        for (int mi = 0; mi < 4; mi++)
#pragma unroll
            for (int ni = 0; ni < 8; ni++) {
                float* a = acc[mi][ni];
                int m = m0 + warp_m * 64 + mi * 16 + rI;
                int n = n0 + warp_n * 64 + ni * 8 + cI;
                *(__half2*)(O + (size_t)m * ldo + n) =
                    __floats2half2_rn(a[0] * alpha, a[1] * alpha);
                *(__half2*)(O + (size_t)(m + 8) * ldo + n) =
                    __floats2half2_rn(a[2] * alpha, a[3] * alpha);
            }
    } else if (EPI == 6) {  // exp(alpha*acc), causal mask, + rowsum atomics
        __half* O = (__half*)O0;
        float rs[4][2];
#pragma unroll
        for (int mi = 0; mi < 4; mi++) { rs[mi][0] = 0.0f; rs[mi][1] = 0.0f; }
#pragma unroll
        for (int mi = 0; mi < 4; mi++)
#pragma unroll
            for (int ni = 0; ni < 8; ni++) {
                float* a = acc[mi][ni];
                int m = m0 + warp_m * 64 + mi * 16 + rI;
                int n = n0 + warp_n * 64 + ni * 8 + cI;
                float e0 = (n     <= m) ? __expf(a[0] * alpha) : 0.0f;
                float e1 = (n + 1 <= m) ? __expf(a[1] * alpha) : 0.0f;
                *(__half2*)(O + (size_t)m * ldo + n) = __floats2half2_rn(e0, e1);
                int m8 = m + 8;
                float e2 = (n     <= m8) ? __expf(a[2] * alpha) : 0.0f;
                float e3 = (n + 1 <= m8) ? __expf(a[3] * alpha) : 0.0f;
                *(__half2*)(O + (size_t)m8 * ldo + n) = __floats2half2_rn(e2, e3);
                rs[mi][0] += e0 + e1;
                rs[mi][1] += e2 + e3;
            }
#pragma unroll
        for (int mi = 0; mi < 4; mi++)
#pragma unroll
            for (int r = 0; r < 2; r++) {
                float v = rs[mi][r];
                v += __shfl_xor_sync(0xFFFFFFFFu, v, 1);
                v += __shfl_xor_sync(0xFFFFFFFFu, v, 2);
                if ((lane & 3) == 0)
                    atomicAdd(&g_rsum[m0 + warp_m * 64 + mi * 16 + rI + r * 8], v);
            }
    } else {  // EPI == 5: fp16 transposed (via fp32 smem staging [128][132])
        __syncthreads();
        float* T = (float*)smem_raw;
#pragma unroll
        for (int mi = 0; mi < 4; mi++)
#pragma unroll
            for (int ni = 0; ni < 8; ni++) {
                float* a = acc[mi][ni];
                int lm = warp_m * 64 + mi * 16 + rI;
                int ln = warp_n * 64 + ni * 8 + cI;
                T[lm * 132 + ln]           = a[0];
                T[lm * 132 + ln + 1]       = a[1];
                T[(lm + 8) * 132 + ln]     = a[2];
                T[(lm + 8) * 132 + ln + 1] = a[3];
            }
        __syncthreads();
        __half* O = (__half*)O0;
        const int n = tid;
#pragma unroll
        for (int i = 0; i < 128; i += 8) {
            __half hp[8];
#pragma unroll
            for (int j = 0; j < 8; j++)
                hp[j] = __float2half_rn(T[(i + j) * 132 + n] * alpha);
            size_t o = (size_t)(n0 + n) * ldo + m0 + i;
            *(uint4*)(O + o) = *(uint4*)hp;
        }
    }
}

// ---------------------------------------------------------------------------
// Stage 0: weight conversions ONLY (minimal gate for k_g).
// b<1024: Wq | b<2048: 32*Wk | else: 32*Wv^T transpose
// ---------------------------------------------------------------------------
__global__ __launch_bounds__(256) void k_convw(
    const float* __restrict__ Wq, const float* __restrict__ Wk,
    const float* __restrict__ Wv)
{
    __shared__ float t[32][33];
    const int b = blockIdx.x;
    const int tid = threadIdx.x;
    if (b < 1024) {
        size_t i = ((size_t)b * 256 + tid) * 4;
        float4 v = *(const float4*)(Wq + i);
        *(__half2*)(g_wq + i)     = __floats2half2_rn(v.x, v.y);
        *(__half2*)(g_wq + i + 2) = __floats2half2_rn(v.z, v.w);
    } else if (b < 2048) {
        size_t i = ((size_t)(b - 1024) * 256 + tid) * 4;
        float4 v = *(const float4*)(Wk + i);
        *(__half2*)(g_wk32 + i)     = __floats2half2_rn(v.x * 32.f, v.y * 32.f);
        *(__half2*)(g_wk32 + i + 2) = __floats2half2_rn(v.z * 32.f, v.w * 32.f);
    } else {
        const int u  = b - 2048;
        const int h0 = (u & 31) * 32, d0 = (u >> 5) * 32;
        const int tx = tid & 31, ty = tid >> 5;
        for (int i = ty; i < 32; i += 8)
            t[i][tx] = Wv[(size_t)(d0 + i) * H + h0 + tx];
        __syncthreads();
        for (int i = ty; i < 32; i += 8)
            g_wvt[(size_t)(h0 + i) * D + d0 + tx] = __float2half_rn(t[tx][i] * 32.f);
    }
}

// ---------------------------------------------------------------------------
// Stage 1: G = 32*Wk @ Wq^T, split-K4 -> fp32 partials in g_s
// ---------------------------------------------------------------------------
__global__ __launch_bounds__(NT, 2) void k_g()
{
    const int gm = blockIdx.y >> 2;
    const int j  = blockIdx.y & 3;
    float* O = (float*)g_s + (size_t)j * (D * D);
    gemm128<2>(g_wk32, H, g_wq, H, (void*)O, D, 1.0f,
               gm * 128, blockIdx.x * 128, j * 256, j * 256 + 256);
}

// ---------------------------------------------------------------------------
// Stage 2: merged convx + G-reduce + rsum-zero (one launch, 4608 blocks):
// b<4096: x->fp16 | else: reduce 4 G partials -> g_g fp16 (+zero g_rsum)
// ---------------------------------------------------------------------------
__global__ __launch_bounds__(256) void k_cxgred(const float* __restrict__ x)
{
    const int b = blockIdx.x;
    const int tid = threadIdx.x;
    if (b < 4096) {
        size_t i = ((size_t)b * 256 + tid) * 4;
        float4 v = *(const float4*)(x + i);
        *(__half2*)(g_x + i)     = __floats2half2_rn(v.x, v.y);
        *(__half2*)(g_x + i + 2) = __floats2half2_rn(v.z, v.w);
    } else {
        const int u = b - 4096;                // 0..511
        if (u == 0) {
#pragma unroll
            for (int j = 0; j < 16; j++) g_rsum[tid * 16 + j] = 0.0f;
        }
        const float* s = (const float*)g_s;
#pragma unroll
        for (int w = 0; w < 2; w++) {
            size_t i = (((size_t)u * 512) + tid * 2 + w) * 4;
            float4 a = *(const float4*)(s + i);
            float4 bb = *(const float4*)(s + (size_t)D * D + i);
            float4 c = *(const float4*)(s + (size_t)2 * D * D + i);
            float4 d = *(const float4*)(s + (size_t)3 * D * D + i);
            *(__half2*)(g_g + i)     = __floats2half2_rn(a.x + bb.x + c.x + d.x,
                                                         a.y + bb.y + c.y + d.y);
            *(__half2*)(g_g + i + 2) = __floats2half2_rn(a.z + bb.z + c.z + d.z,
                                                         a.w + bb.w + c.w + d.w);
        }
    }
}

// ---------------------------------------------------------------------------
// Stage 3: merged v^T and t (uniform 32-chunk CTAs, 512 total)
// ---------------------------------------------------------------------------
__global__ __launch_bounds__(NT, 2) void k_vt()
{
    const int by = blockIdx.y, bx = blockIdx.x;
    if (by < 32) {
        gemm128<5>(g_x, D, g_wvt, D, (void*)g_vt, L, 0.03125f,
                   by * 128, bx * 128, 0, D);
    } else {
        gemm128<3>(g_x, D, g_g, D, (void*)g_t, D, 1.0f,
                   (by - 32) * 128, bx * 128, 0, D);
    }
}

// ---------------------------------------------------------------------------
// Stage 4: P' = exp(t.x^T / 1024), causal mask, + rowsum atomics.
// 1-D triangular grid: exactly 528 CTAs.
// ---------------------------------------------------------------------------
__global__ __launch_bounds__(NT, 2) void k_scores()
{
    const int u = blockIdx.x;
    int by = (int)((__fsqrt_rn(8.0f * (float)u + 1.0f) - 1.0f) * 0.5f);
    while ((by + 1) * (by + 2) / 2 <= u) by++;
    while (by * (by + 1) / 2 > u)        by--;
    const int bx = u - by * (by + 1) / 2;
    gemm128<6>(g_t, D, g_x, D, (void*)g_p, L, 1.0f / 1024.0f,
               by * 128, bx * 128, 0, D);
}

// ---------------------------------------------------------------------------
// Stage 5: out = P' @ v (unnormalized), balanced split-K (pieces <= 32 chunks)
// ---------------------------------------------------------------------------
__global__ __launch_bounds__(NT, 2) void k_pv(float* __restrict__ out)
{
    const int y = blockIdx.y, x = blockIdx.x;
    int bi, j, np;
    if (y < 32)      { bi = 31 - (y >> 2);        j = y & 3;          np = 4; }
    else if (y < 56) { int u = y - 32; bi = 23 - u / 3; j = u % 3;    np = 3; }
    else if (y < 72) { int u = y - 56; bi = 15 - (u >> 1); j = u & 1; np = 2; }
    else             { bi = 7 - (y - 72);         j = 0;              np = 1; }

    const int Kc = (bi + 1) * 4;
    const int kb = (j * Kc) / np * 32;
    const int ke = ((j + 1) * Kc) / np * 32;
    const int m0 = bi * 128, n0 = x * 128;

    if (j == 0) {
        gemm128<2>(g_p, L, g_vt, L, (void*)out, H, 1.0f, m0, n0, kb, ke);
    } else {
        int sl;
        if (bi < 16)      sl = bi - 8;
        else if (bi < 24) sl = 8 + (bi - 16) * 2 + (j - 1);
        else              sl = 24 + (bi - 24) * 3 + (j - 1);
        float* base = (float*)g_s + (size_t)(sl * 8 + x) * 16384;
        float* O = base - (size_t)m0 * 128 - n0;
        gemm128<2>(g_p, L, g_vt, L, (void*)O, 128, 1.0f, m0, n0, kb, ke);
    }
}

// ---------------------------------------------------------------------------
// Stage 6: one block per output row m: merge split-K partials, scale by
// 1/g_rsum[m] (sums accumulated by the scores epilogue).
// ---------------------------------------------------------------------------
__global__ __launch_bounds__(256) void k_pvscale(float* __restrict__ out)
{
    const int m   = blockIdx.x;
    const int tid = threadIdx.x;
    const float inv = 1.0f / g_rsum[m];

    const int n  = tid * 4;
    const int bi = m >> 7;
    const int np = (bi >> 3) + 1;
    size_t oi = (size_t)m * H + n;

    float4 a = *(float4*)(out + oi);
    if (np > 1) {
        const int r128 = m & 127;
        const int xt = n >> 7;
        const int nl = n & 127;
        const float* s = (const float*)g_s;
#pragma unroll 3
        for (int j = 1; j < 4; j++) {
            if (j >= np) break;
            int sl;
            if (bi < 16)      sl = bi - 8;
            else if (bi < 24) sl = 8 + (bi - 16) * 2 + (j - 1);
            else              sl = 24 + (bi - 24) * 3 + (j - 1);
            const float* b = s + (size_t)(sl * 8 + xt) * 16384 + r128 * 128 + nl;
            float4 v = *(const float4*)b;
            a.x += v.x; a.y += v.y; a.z += v.z; a.w += v.w;
        }
    }
    a.x *= inv; a.y *= inv; a.z *= inv; a.w *= inv;
    *(float4*)(out + oi) = a;
}

// ---------------------------------------------------------------------------
extern "C" void kernel_launch(void* const* d_in, const int* in_sizes, int n_in,
                              void* d_out, int out_size)
{
    const float* x  = (const float*)d_in[0];
    // d_in[1] = mask (structurally triu(k=1); causality handled directly)
    const float* Wq = (const float*)d_in[2];
    const float* Wk = (const float*)d_in[3];
    const float* Wv = (const float*)d_in[4];
    float* out = (float*)d_out;

    cudaFuncSetAttribute(k_vt, cudaFuncAttributeMaxDynamicSharedMemorySize, SMEM_QKV);

    k_convw<<<3072, 256>>>(Wq, Wk, Wv);
    k_g<<<dim3(8, 32), NT, SMEM_G>>>();
    k_cxgred<<<4608, 256>>>(x);
    k_vt<<<dim3(8, 64), NT, SMEM_QKV>>>();
    k_scores<<<528, NT, SMEM_G>>>();
    k_pv<<<dim3(8, 80), NT, SMEM_G>>>(out);
    k_pvscale<<<L, 256>>>(out);
}